// round 1
// baseline (speedup 1.0000x reference)
#include <cuda_runtime.h>
#include <cuda_bf16.h>

// Problem constants
#define VOCAB 32000
#define DMODEL 1024
#define NHEAD 16
#define HDIM 64
#define FFDIM 4096
#define NLAYER 4
#define SEQ 2048
#define BATCH 2
#define MTOK (BATCH * SEQ)      // 4096 token rows
#define HK (NHEAD * HDIM)       // 1024

// ---------------------------------------------------------------------------
// Scratch (device globals; no allocations allowed)
// ---------------------------------------------------------------------------
__device__ float g_x[MTOK * DMODEL];     // activations (residual stream)
__device__ float g_q[MTOK * HK];
__device__ float g_k[MTOK * HK];
__device__ float g_v[MTOK * HK];
__device__ float g_attn[MTOK * HK];
__device__ float g_ffn[MTOK * FFDIM];    // 64MB

// ---------------------------------------------------------------------------
// Embedding: x[b,s,:] = emb[tokens[b,s]] + pos_emb[s]
// ---------------------------------------------------------------------------
__global__ void embed_kernel(const int* __restrict__ tokens,
                             const float* __restrict__ emb,
                             const float* __restrict__ pos,
                             float* __restrict__ x)
{
    int row = blockIdx.x;            // b*SEQ + s
    int s = row & (SEQ - 1);
    int t = tokens[row];
    const float4* e = (const float4*)(emb + (long)t * DMODEL);
    const float4* p = (const float4*)(pos + (long)s * DMODEL);
    float4* xp = (float4*)(x + (long)row * DMODEL);
    for (int d = threadIdx.x; d < DMODEL / 4; d += blockDim.x) {
        float4 a = e[d], b = p[d];
        a.x += b.x; a.y += b.y; a.z += b.z; a.w += b.w;
        xp[d] = a;
    }
}

// ---------------------------------------------------------------------------
// SGEMM: C[M,N] = A[M,K] @ B[K,N] + bias[N]  (+ optional ReLU, + optional resid)
// BM=BN=128, BK=8, 256 threads, 8x8 micro-tile per thread.
// Requires: M%128==0, N%128==0, K%8==0 (all shapes here satisfy this).
// ---------------------------------------------------------------------------
#define BM 128
#define BN 128
#define BKD 8
#define TM 8
#define TN 8

template<bool RELU, bool RESID>
__global__ __launch_bounds__(256)
void sgemm_kernel(const float* __restrict__ A, const float* __restrict__ B,
                  const float* __restrict__ bias, const float* __restrict__ resid,
                  float* __restrict__ C, int M, int N, int Kd)
{
    __shared__ float As[BKD][BM];
    __shared__ float Bs[BKD][BN];

    int tid = threadIdx.x;
    int tx = tid & 15;        // 0..15
    int ty = tid >> 4;        // 0..15
    int row0 = blockIdx.y * BM;
    int col0 = blockIdx.x * BN;

    // global load mapping (one float4 of each tile per thread)
    int arow = tid >> 1;              // 0..127
    int acol = (tid & 1) * 4;         // 0 or 4
    int brow = tid >> 5;              // 0..7
    int bcol = (tid & 31) * 4;        // 0..124

    const float* Aptr = A + (long)(row0 + arow) * Kd + acol;
    const float* Bptr = B + (long)brow * N + col0 + bcol;

    float acc[TM][TN];
#pragma unroll
    for (int i = 0; i < TM; i++)
#pragma unroll
        for (int j = 0; j < TN; j++) acc[i][j] = 0.f;

    for (int kb = 0; kb < Kd; kb += BKD) {
        float4 a4 = *(const float4*)Aptr; Aptr += BKD;
        float4 b4 = *(const float4*)Bptr; Bptr += (long)BKD * N;

        As[acol + 0][arow] = a4.x;
        As[acol + 1][arow] = a4.y;
        As[acol + 2][arow] = a4.z;
        As[acol + 3][arow] = a4.w;
        *(float4*)&Bs[brow][bcol] = b4;
        __syncthreads();

#pragma unroll
        for (int k = 0; k < BKD; k++) {
            float ar[TM], br[TN];
            *(float4*)&ar[0] = *(const float4*)&As[k][ty * TM];
            *(float4*)&ar[4] = *(const float4*)&As[k][ty * TM + 4];
            *(float4*)&br[0] = *(const float4*)&Bs[k][tx * TN];
            *(float4*)&br[4] = *(const float4*)&Bs[k][tx * TN + 4];
#pragma unroll
            for (int i = 0; i < TM; i++)
#pragma unroll
                for (int j = 0; j < TN; j++)
                    acc[i][j] = fmaf(ar[i], br[j], acc[i][j]);
        }
        __syncthreads();
    }

    // epilogue
#pragma unroll
    for (int i = 0; i < TM; i++) {
        int r = row0 + ty * TM + i;
#pragma unroll
        for (int j = 0; j < TN; j += 4) {
            int c = col0 + tx * TN + j;
            float4 v;
            v.x = acc[i][j + 0] + bias[c + 0];
            v.y = acc[i][j + 1] + bias[c + 1];
            v.z = acc[i][j + 2] + bias[c + 2];
            v.w = acc[i][j + 3] + bias[c + 3];
            if (RELU) {
                v.x = fmaxf(v.x, 0.f); v.y = fmaxf(v.y, 0.f);
                v.z = fmaxf(v.z, 0.f); v.w = fmaxf(v.w, 0.f);
            }
            if (RESID) {
                float4 rr = *(const float4*)&resid[(long)r * N + c];
                v.x += rr.x; v.y += rr.y; v.z += rr.z; v.w += rr.w;
            }
            *(float4*)&C[(long)r * N + c] = v;
        }
    }
}

// ---------------------------------------------------------------------------
// Causal attention, one (b, h, q) row per block, 128 threads.
// Layouts: Q/K/V/O are [B*S, H*K] with head offset h*HDIM.
// ---------------------------------------------------------------------------
__global__ __launch_bounds__(128)
void attn_kernel(const float* __restrict__ Q, const float* __restrict__ Km,
                 const float* __restrict__ Vm, float* __restrict__ O)
{
    __shared__ float qs[HDIM];
    __shared__ float sc[SEQ];
    __shared__ float red[128];
    __shared__ float part[128];

    int qi = blockIdx.x;
    int bh = blockIdx.y;
    int b = bh >> 4;           // / NHEAD
    int h = bh & 15;           // % NHEAD
    int tid = threadIdx.x;

    long base = (long)b * SEQ * HK + h * HDIM;  // add s*HK per row
    const float* qp = Q + base + (long)qi * HK;
    if (tid < HDIM) qs[tid] = qp[tid];
    __syncthreads();

    int n = qi + 1;            // causal: keys 0..qi
    float m = -1e30f;
    for (int s = tid; s < n; s += 128) {
        const float* kp = Km + base + (long)s * HK;
        float d = 0.f;
#pragma unroll 16
        for (int k = 0; k < HDIM; k++) d = fmaf(qs[k], kp[k], d);
        d *= 0.125f;           // 1/sqrt(64)
        sc[s] = d;
        m = fmaxf(m, d);
    }
    red[tid] = m;
    __syncthreads();
#pragma unroll
    for (int off = 64; off > 0; off >>= 1) {
        if (tid < off) red[tid] = fmaxf(red[tid], red[tid + off]);
        __syncthreads();
    }
    m = red[0];
    __syncthreads();

    float ssum = 0.f;
    for (int s = tid; s < n; s += 128) {
        float e = __expf(sc[s] - m);
        sc[s] = e;
        ssum += e;
    }
    red[tid] = ssum;
    __syncthreads();
#pragma unroll
    for (int off = 64; off > 0; off >>= 1) {
        if (tid < off) red[tid] += red[tid + off];
        __syncthreads();
    }
    float inv = 1.0f / red[0];

    // phase 3: output.  k = tid%64, half = tid/64 splits the s-range.
    int k = tid & 63;
    int half = tid >> 6;
    float acc = 0.f;
    for (int s = half; s < n; s += 2)
        acc = fmaf(sc[s], Vm[base + (long)s * HK + k], acc);
    part[tid] = acc;
    __syncthreads();
    if (tid < HDIM)
        O[base + (long)qi * HK + k] = (part[tid] + part[tid + 64]) * inv;
}

// ---------------------------------------------------------------------------
// Launch
// ---------------------------------------------------------------------------
extern "C" void kernel_launch(void* const* d_in, const int* in_sizes, int n_in,
                              void* d_out, int out_size)
{
    const int*   tokens = (const int*)  d_in[0];
    const float* emb    = (const float*)d_in[1];
    const float* pos    = (const float*)d_in[2];
    const float* Wq     = (const float*)d_in[3];
    const float* bq     = (const float*)d_in[4];
    const float* Wk     = (const float*)d_in[5];
    const float* bk     = (const float*)d_in[6];
    const float* Wv     = (const float*)d_in[7];
    const float* bv     = (const float*)d_in[8];
    const float* Wo     = (const float*)d_in[9];
    const float* bo     = (const float*)d_in[10];
    const float* W1     = (const float*)d_in[11];
    const float* b1     = (const float*)d_in[12];
    const float* W2     = (const float*)d_in[13];
    const float* b2     = (const float*)d_in[14];
    const float* Wf     = (const float*)d_in[15];
    const float* bf     = (const float*)d_in[16];
    float* out = (float*)d_out;

    float *x, *q, *k, *v, *a, *f;
    cudaGetSymbolAddress((void**)&x, g_x);
    cudaGetSymbolAddress((void**)&q, g_q);
    cudaGetSymbolAddress((void**)&k, g_k);
    cudaGetSymbolAddress((void**)&v, g_v);
    cudaGetSymbolAddress((void**)&a, g_attn);
    cudaGetSymbolAddress((void**)&f, g_ffn);

    embed_kernel<<<MTOK, 256>>>(tokens, emb, pos, x);

    dim3 gProj(HK / BN, MTOK / BM);        // 1024-wide GEMMs
    dim3 gFF1(FFDIM / BN, MTOK / BM);      // 4096-wide
    dim3 gAttn(SEQ, BATCH * NHEAD);

    for (int l = 0; l < NLAYER; l++) {
        const float* Wq_l = Wq + (long)l * DMODEL * HK;
        const float* Wk_l = Wk + (long)l * DMODEL * HK;
        const float* Wv_l = Wv + (long)l * DMODEL * HK;
        const float* Wo_l = Wo + (long)l * HK * DMODEL;
        const float* W1_l = W1 + (long)l * DMODEL * FFDIM;
        const float* W2_l = W2 + (long)l * FFDIM * DMODEL;
        const float* bq_l = bq + (long)l * HK;
        const float* bk_l = bk + (long)l * HK;
        const float* bv_l = bv + (long)l * HK;
        const float* bo_l = bo + (long)l * DMODEL;
        const float* b1_l = b1 + (long)l * FFDIM;
        const float* b2_l = b2 + (long)l * DMODEL;

        sgemm_kernel<false, false><<<gProj, 256>>>(x, Wq_l, bq_l, nullptr, q, MTOK, HK, DMODEL);
        sgemm_kernel<false, false><<<gProj, 256>>>(x, Wk_l, bk_l, nullptr, k, MTOK, HK, DMODEL);
        sgemm_kernel<false, false><<<gProj, 256>>>(x, Wv_l, bv_l, nullptr, v, MTOK, HK, DMODEL);

        attn_kernel<<<gAttn, 128>>>(q, k, v, a);

        // x = x + a @ Wo + bo   (resid = x, write into x)
        sgemm_kernel<false, true><<<gProj, 256>>>(a, Wo_l, bo_l, x, x, MTOK, DMODEL, HK);
        // ffn = relu(x @ W1 + b1)
        sgemm_kernel<true, false><<<gFF1, 256>>>(x, W1_l, b1_l, nullptr, f, MTOK, FFDIM, DMODEL);
        // x = x + ffn @ W2 + b2
        sgemm_kernel<false, true><<<gProj, 256>>>(f, W2_l, b2_l, x, x, MTOK, DMODEL, FFDIM);
    }

    // logits = x @ Wf + bf   -> d_out [B,S,V]
    dim3 gF(VOCAB / BN, MTOK / BM);        // 250 x 32
    sgemm_kernel<false, false><<<gF, 256>>>(x, Wf, bf, nullptr, out, MTOK, VOCAB, DMODEL);
}

// round 2
// speedup vs baseline: 4.0578x; 4.0578x over previous
#include <cuda_runtime.h>
#include <cuda_bf16.h>

// Problem constants
#define VOCAB 32000
#define DMODEL 1024
#define NHEAD 16
#define HDIM 64
#define FFDIM 4096
#define NLAYER 4
#define SEQ 2048
#define BATCH 2
#define MTOK (BATCH * SEQ)      // 4096 token rows
#define HK (NHEAD * HDIM)       // 1024

// ---------------------------------------------------------------------------
// Scratch (device globals; no allocations allowed)
// ---------------------------------------------------------------------------
__device__ float g_x[MTOK * DMODEL];
__device__ float g_q[MTOK * HK];
__device__ float g_k[MTOK * HK];
__device__ float g_v[MTOK * HK];
__device__ float g_attn[MTOK * HK];
__device__ float g_ffn[MTOK * FFDIM];

// ---------------------------------------------------------------------------
// Embedding
// ---------------------------------------------------------------------------
__global__ void embed_kernel(const int* __restrict__ tokens,
                             const float* __restrict__ emb,
                             const float* __restrict__ pos,
                             float* __restrict__ x)
{
    int row = blockIdx.x;
    int s = row & (SEQ - 1);
    int t = tokens[row];
    const float4* e = (const float4*)(emb + (long)t * DMODEL);
    const float4* p = (const float4*)(pos + (long)s * DMODEL);
    float4* xp = (float4*)(x + (long)row * DMODEL);
    for (int d = threadIdx.x; d < DMODEL / 4; d += blockDim.x) {
        float4 a = e[d], b = p[d];
        a.x += b.x; a.y += b.y; a.z += b.z; a.w += b.w;
        xp[d] = a;
    }
}

// ---------------------------------------------------------------------------
// SGEMM (unchanged from round 1)
// ---------------------------------------------------------------------------
#define BM 128
#define BN 128
#define BKD 8
#define TM 8
#define TN 8

template<bool RELU, bool RESID>
__global__ __launch_bounds__(256)
void sgemm_kernel(const float* __restrict__ A, const float* __restrict__ B,
                  const float* __restrict__ bias, const float* __restrict__ resid,
                  float* __restrict__ C, int M, int N, int Kd)
{
    __shared__ float As[BKD][BM];
    __shared__ float Bs[BKD][BN];

    int tid = threadIdx.x;
    int tx = tid & 15;
    int ty = tid >> 4;
    int row0 = blockIdx.y * BM;
    int col0 = blockIdx.x * BN;

    int arow = tid >> 1;
    int acol = (tid & 1) * 4;
    int brow = tid >> 5;
    int bcol = (tid & 31) * 4;

    const float* Aptr = A + (long)(row0 + arow) * Kd + acol;
    const float* Bptr = B + (long)brow * N + col0 + bcol;

    float acc[TM][TN];
#pragma unroll
    for (int i = 0; i < TM; i++)
#pragma unroll
        for (int j = 0; j < TN; j++) acc[i][j] = 0.f;

    for (int kb = 0; kb < Kd; kb += BKD) {
        float4 a4 = *(const float4*)Aptr; Aptr += BKD;
        float4 b4 = *(const float4*)Bptr; Bptr += (long)BKD * N;

        As[acol + 0][arow] = a4.x;
        As[acol + 1][arow] = a4.y;
        As[acol + 2][arow] = a4.z;
        As[acol + 3][arow] = a4.w;
        *(float4*)&Bs[brow][bcol] = b4;
        __syncthreads();

#pragma unroll
        for (int k = 0; k < BKD; k++) {
            float ar[TM], br[TN];
            *(float4*)&ar[0] = *(const float4*)&As[k][ty * TM];
            *(float4*)&ar[4] = *(const float4*)&As[k][ty * TM + 4];
            *(float4*)&br[0] = *(const float4*)&Bs[k][tx * TN];
            *(float4*)&br[4] = *(const float4*)&Bs[k][tx * TN + 4];
#pragma unroll
            for (int i = 0; i < TM; i++)
#pragma unroll
                for (int j = 0; j < TN; j++)
                    acc[i][j] = fmaf(ar[i], br[j], acc[i][j]);
        }
        __syncthreads();
    }

#pragma unroll
    for (int i = 0; i < TM; i++) {
        int r = row0 + ty * TM + i;
#pragma unroll
        for (int j = 0; j < TN; j += 4) {
            int c = col0 + tx * TN + j;
            float4 v;
            v.x = acc[i][j + 0] + bias[c + 0];
            v.y = acc[i][j + 1] + bias[c + 1];
            v.z = acc[i][j + 2] + bias[c + 2];
            v.w = acc[i][j + 3] + bias[c + 3];
            if (RELU) {
                v.x = fmaxf(v.x, 0.f); v.y = fmaxf(v.y, 0.f);
                v.z = fmaxf(v.z, 0.f); v.w = fmaxf(v.w, 0.f);
            }
            if (RESID) {
                float4 rr = *(const float4*)&resid[(long)r * N + c];
                v.x += rr.x; v.y += rr.y; v.z += rr.z; v.w += rr.w;
            }
            *(float4*)&C[(long)r * N + c] = v;
        }
    }
}

// ---------------------------------------------------------------------------
// Flash attention: 64 q-rows x one head per CTA, 64-key tiles, online softmax.
// 256 threads = 16x16 grid. Each thread: 4x4 S-tile (kc = tx + 16*j, strided)
// and 4x4 O-tile (dims d = tx*4..+3), rows q = ty*4..+3 for both.
// ---------------------------------------------------------------------------
#define FPAD 68   // row stride in floats (bank-conflict padding, 16B aligned)

__global__ __launch_bounds__(256)
void flash_attn_kernel(const float* __restrict__ Q, const float* __restrict__ K,
                       const float* __restrict__ V, float* __restrict__ O)
{
    extern __shared__ float sm[];
    float* Qs = sm;                    // [64][FPAD]
    float* Ks = sm + 64 * FPAD;
    float* Vs = sm + 2 * 64 * FPAD;
    float* Ps = sm + 3 * 64 * FPAD;

    int qt = gridDim.x - 1 - blockIdx.x;   // schedule heavy tiles first
    int bh = blockIdx.y;
    int b = bh >> 4;
    int h = bh & 15;
    int tid = threadIdx.x;
    int tx = tid & 15;
    int ty = tid >> 4;

    long base = (long)b * SEQ * HK + h * HDIM;

    // Load Q tile (coalesced float4). Covered by first in-loop sync.
    for (int i = tid; i < 64 * 16; i += 256) {
        int r = i >> 4, c4 = (i & 15) * 4;
        *(float4*)&Qs[r * FPAD + c4] =
            *(const float4*)&Q[base + (long)(qt * 64 + r) * HK + c4];
    }

    float m[4], l[4], o[4][4];
#pragma unroll
    for (int i = 0; i < 4; i++) {
        m[i] = -1e30f; l[i] = 0.f;
#pragma unroll
        for (int j = 0; j < 4; j++) o[i][j] = 0.f;
    }

    for (int jt = 0; jt <= qt; jt++) {
        // Load K and V tiles
        for (int i = tid; i < 64 * 16; i += 256) {
            int r = i >> 4, c4 = (i & 15) * 4;
            long g = base + (long)(jt * 64 + r) * HK + c4;
            *(float4*)&Ks[r * FPAD + c4] = *(const float4*)&K[g];
            *(float4*)&Vs[r * FPAD + c4] = *(const float4*)&V[g];
        }
        __syncthreads();

        // S = Q K^T  (4x4 per thread; kc = tx + 16*j)
        float s[4][4];
#pragma unroll
        for (int i = 0; i < 4; i++)
#pragma unroll
            for (int j = 0; j < 4; j++) s[i][j] = 0.f;

#pragma unroll 4
        for (int k4 = 0; k4 < HDIM; k4 += 4) {
            float4 qv[4], kv[4];
#pragma unroll
            for (int i = 0; i < 4; i++)
                qv[i] = *(const float4*)&Qs[(ty * 4 + i) * FPAD + k4];
#pragma unroll
            for (int j = 0; j < 4; j++)
                kv[j] = *(const float4*)&Ks[(tx + 16 * j) * FPAD + k4];
#pragma unroll
            for (int i = 0; i < 4; i++)
#pragma unroll
                for (int j = 0; j < 4; j++) {
                    s[i][j] = fmaf(qv[i].x, kv[j].x, s[i][j]);
                    s[i][j] = fmaf(qv[i].y, kv[j].y, s[i][j]);
                    s[i][j] = fmaf(qv[i].z, kv[j].z, s[i][j]);
                    s[i][j] = fmaf(qv[i].w, kv[j].w, s[i][j]);
                }
        }

        // scale + causal mask (only diagonal tile needs masking)
        if (jt == qt) {
#pragma unroll
            for (int i = 0; i < 4; i++) {
                int qloc = ty * 4 + i;
#pragma unroll
                for (int j = 0; j < 4; j++) {
                    int kloc = tx + 16 * j;
                    s[i][j] = (kloc > qloc) ? -1e30f : s[i][j] * 0.125f;
                }
            }
        } else {
#pragma unroll
            for (int i = 0; i < 4; i++)
#pragma unroll
                for (int j = 0; j < 4; j++) s[i][j] *= 0.125f;
        }

        // Online softmax update (rows distributed over tx: 16-lane shfl reduce)
#pragma unroll
        for (int i = 0; i < 4; i++) {
            float rmax = fmaxf(fmaxf(s[i][0], s[i][1]), fmaxf(s[i][2], s[i][3]));
#pragma unroll
            for (int w = 1; w < 16; w <<= 1)
                rmax = fmaxf(rmax, __shfl_xor_sync(0xffffffffu, rmax, w));
            float mn = fmaxf(m[i], rmax);
            float corr = __expf(m[i] - mn);
            float rsum = 0.f;
#pragma unroll
            for (int j = 0; j < 4; j++) {
                float p = __expf(s[i][j] - mn);
                s[i][j] = p;
                rsum += p;
            }
#pragma unroll
            for (int w = 1; w < 16; w <<= 1)
                rsum += __shfl_xor_sync(0xffffffffu, rsum, w);
            l[i] = l[i] * corr + rsum;
            m[i] = mn;
#pragma unroll
            for (int j = 0; j < 4; j++) o[i][j] *= corr;
        }

        // P to smem (scattered cols, conflict-free across warp)
#pragma unroll
        for (int i = 0; i < 4; i++)
#pragma unroll
            for (int j = 0; j < 4; j++)
                Ps[(ty * 4 + i) * FPAD + tx + 16 * j] = s[i][j];
        __syncthreads();

        // O += P V  (dims d = tx*4..+3)
#pragma unroll 4
        for (int k4 = 0; k4 < 64; k4 += 4) {
            float4 pv[4];
#pragma unroll
            for (int i = 0; i < 4; i++)
                pv[i] = *(const float4*)&Ps[(ty * 4 + i) * FPAD + k4];
#pragma unroll
            for (int c = 0; c < 4; c++) {
                float4 vv = *(const float4*)&Vs[(k4 + c) * FPAD + tx * 4];
#pragma unroll
                for (int i = 0; i < 4; i++) {
                    float p = (c == 0) ? pv[i].x : (c == 1) ? pv[i].y
                              : (c == 2) ? pv[i].z : pv[i].w;
                    o[i][0] = fmaf(p, vv.x, o[i][0]);
                    o[i][1] = fmaf(p, vv.y, o[i][1]);
                    o[i][2] = fmaf(p, vv.z, o[i][2]);
                    o[i][3] = fmaf(p, vv.w, o[i][3]);
                }
            }
        }
        __syncthreads();   // before next tile overwrites Ks/Vs/Ps
    }

    // Write O / l
#pragma unroll
    for (int i = 0; i < 4; i++) {
        float inv = 1.0f / l[i];
        int qg = qt * 64 + ty * 4 + i;
        float4 ov;
        ov.x = o[i][0] * inv; ov.y = o[i][1] * inv;
        ov.z = o[i][2] * inv; ov.w = o[i][3] * inv;
        *(float4*)&O[base + (long)qg * HK + tx * 4] = ov;
    }
}

#define FLASH_SMEM (4 * 64 * FPAD * 4)   // 69632 bytes

// ---------------------------------------------------------------------------
// Launch
// ---------------------------------------------------------------------------
extern "C" void kernel_launch(void* const* d_in, const int* in_sizes, int n_in,
                              void* d_out, int out_size)
{
    const int*   tokens = (const int*)  d_in[0];
    const float* emb    = (const float*)d_in[1];
    const float* pos    = (const float*)d_in[2];
    const float* Wq     = (const float*)d_in[3];
    const float* bq     = (const float*)d_in[4];
    const float* Wk     = (const float*)d_in[5];
    const float* bk     = (const float*)d_in[6];
    const float* Wv     = (const float*)d_in[7];
    const float* bv     = (const float*)d_in[8];
    const float* Wo     = (const float*)d_in[9];
    const float* bo     = (const float*)d_in[10];
    const float* W1     = (const float*)d_in[11];
    const float* b1     = (const float*)d_in[12];
    const float* W2     = (const float*)d_in[13];
    const float* b2     = (const float*)d_in[14];
    const float* Wf     = (const float*)d_in[15];
    const float* bf     = (const float*)d_in[16];
    float* out = (float*)d_out;

    float *x, *q, *k, *v, *a, *f;
    cudaGetSymbolAddress((void**)&x, g_x);
    cudaGetSymbolAddress((void**)&q, g_q);
    cudaGetSymbolAddress((void**)&k, g_k);
    cudaGetSymbolAddress((void**)&v, g_v);
    cudaGetSymbolAddress((void**)&a, g_attn);
    cudaGetSymbolAddress((void**)&f, g_ffn);

    static bool attr_set = false;
    if (!attr_set) {
        cudaFuncSetAttribute(flash_attn_kernel,
                             cudaFuncAttributeMaxDynamicSharedMemorySize,
                             FLASH_SMEM);
        attr_set = true;
    }

    embed_kernel<<<MTOK, 256>>>(tokens, emb, pos, x);

    dim3 gProj(HK / BN, MTOK / BM);
    dim3 gFF1(FFDIM / BN, MTOK / BM);
    dim3 gAttn(SEQ / 64, BATCH * NHEAD);   // 32 x 32

    for (int l = 0; l < NLAYER; l++) {
        const float* Wq_l = Wq + (long)l * DMODEL * HK;
        const float* Wk_l = Wk + (long)l * DMODEL * HK;
        const float* Wv_l = Wv + (long)l * DMODEL * HK;
        const float* Wo_l = Wo + (long)l * HK * DMODEL;
        const float* W1_l = W1 + (long)l * DMODEL * FFDIM;
        const float* W2_l = W2 + (long)l * FFDIM * DMODEL;
        const float* bq_l = bq + (long)l * HK;
        const float* bk_l = bk + (long)l * HK;
        const float* bv_l = bv + (long)l * HK;
        const float* bo_l = bo + (long)l * DMODEL;
        const float* b1_l = b1 + (long)l * FFDIM;
        const float* b2_l = b2 + (long)l * DMODEL;

        sgemm_kernel<false, false><<<gProj, 256>>>(x, Wq_l, bq_l, nullptr, q, MTOK, HK, DMODEL);
        sgemm_kernel<false, false><<<gProj, 256>>>(x, Wk_l, bk_l, nullptr, k, MTOK, HK, DMODEL);
        sgemm_kernel<false, false><<<gProj, 256>>>(x, Wv_l, bv_l, nullptr, v, MTOK, HK, DMODEL);

        flash_attn_kernel<<<gAttn, 256, FLASH_SMEM>>>(q, k, v, a);

        sgemm_kernel<false, true><<<gProj, 256>>>(a, Wo_l, bo_l, x, x, MTOK, DMODEL, HK);
        sgemm_kernel<true, false><<<gFF1, 256>>>(x, W1_l, b1_l, nullptr, f, MTOK, FFDIM, DMODEL);
        sgemm_kernel<false, true><<<gProj, 256>>>(f, W2_l, b2_l, x, x, MTOK, DMODEL, FFDIM);
    }

    dim3 gF(VOCAB / BN, MTOK / BM);
    sgemm_kernel<false, false><<<gF, 256>>>(x, Wf, bf, nullptr, out, MTOK, VOCAB, DMODEL);
}

// round 4
// speedup vs baseline: 8.0994x; 1.9960x over previous
#include <cuda_runtime.h>
#include <cuda_bf16.h>
#include <cstdint>

// Problem constants
#define VOCAB 32000
#define DMODEL 1024
#define NHEAD 16
#define HDIM 64
#define FFDIM 4096
#define NLAYER 4
#define SEQ 2048
#define BATCH 2
#define MTOK (BATCH * SEQ)      // 4096 token rows
#define HK (NHEAD * HDIM)       // 1024
#define QKVN 3072               // fused q|k|v output width

// ---------------------------------------------------------------------------
// Scratch (device globals; no allocations allowed)
// ---------------------------------------------------------------------------
__device__ float g_x[MTOK * DMODEL];                 // residual stream fp32
__device__ float g_qkv[MTOK * QKVN];                 // fused qkv fp32
__device__ float g_qkvb[NLAYER * QKVN];              // fused qkv bias
__device__ __nv_bfloat16 g_xh[MTOK * DMODEL], g_xl[MTOK * DMODEL];
__device__ __nv_bfloat16 g_ah[MTOK * HK],     g_al[MTOK * HK];
__device__ __nv_bfloat16 g_fh[MTOK * FFDIM],  g_fl[MTOK * FFDIM];
// transposed bf16 weights [N,K] hi/lo
__device__ __nv_bfloat16 g_wqkvh[NLAYER * QKVN * DMODEL], g_wqkvl[NLAYER * QKVN * DMODEL];
__device__ __nv_bfloat16 g_woh[NLAYER * DMODEL * HK],     g_wol[NLAYER * DMODEL * HK];
__device__ __nv_bfloat16 g_w1h[NLAYER * FFDIM * DMODEL],  g_w1l[NLAYER * FFDIM * DMODEL];
__device__ __nv_bfloat16 g_w2h[NLAYER * DMODEL * FFDIM],  g_w2l[NLAYER * DMODEL * FFDIM];
__device__ __nv_bfloat16 g_wfh[VOCAB * DMODEL],           g_wfl[VOCAB * DMODEL];

// ---------------------------------------------------------------------------
// PTX helpers (all sm_80-era, arch-portable)
// ---------------------------------------------------------------------------
__device__ __forceinline__ uint32_t smem_u32(const void* p) {
    return (uint32_t)__cvta_generic_to_shared(p);
}
__device__ __forceinline__ void cp_async16(uint32_t dst, const void* src) {
    asm volatile("cp.async.cg.shared.global [%0], [%1], 16;\n" :: "r"(dst), "l"(src));
}
__device__ __forceinline__ void cp_commit() { asm volatile("cp.async.commit_group;\n" ::: "memory"); }
template<int N> __device__ __forceinline__ void cp_wait() {
    asm volatile("cp.async.wait_group %0;\n" :: "n"(N) : "memory");
}
__device__ __forceinline__ void ldsm_x4(uint32_t* r, uint32_t addr) {
    asm volatile("ldmatrix.sync.aligned.m8n8.x4.shared.b16 {%0,%1,%2,%3}, [%4];"
                 : "=r"(r[0]), "=r"(r[1]), "=r"(r[2]), "=r"(r[3]) : "r"(addr));
}
__device__ __forceinline__ void mma_bf16(float* c, const uint32_t* a, const uint32_t* b) {
    asm volatile(
        "mma.sync.aligned.m16n8k16.row.col.f32.bf16.bf16.f32 "
        "{%0,%1,%2,%3}, {%4,%5,%6,%7}, {%8,%9}, {%0,%1,%2,%3};"
        : "+f"(c[0]), "+f"(c[1]), "+f"(c[2]), "+f"(c[3])
        : "r"(a[0]), "r"(a[1]), "r"(a[2]), "r"(a[3]), "r"(b[0]), "r"(b[1]));
}

// ---------------------------------------------------------------------------
// bf16 hi/lo split helpers
// ---------------------------------------------------------------------------
__device__ __forceinline__ void split_bf16(float v, __nv_bfloat16& h, __nv_bfloat16& l) {
    h = __float2bfloat16(v);
    l = __float2bfloat16(v - __bfloat162float(h));
}

// ---------------------------------------------------------------------------
// Embedding: x = emb[token] + pos ; also writes bf16 hi/lo
// ---------------------------------------------------------------------------
__global__ void embed_kernel(const int* __restrict__ tokens,
                             const float* __restrict__ emb,
                             const float* __restrict__ pos,
                             float* __restrict__ x,
                             __nv_bfloat16* __restrict__ xh,
                             __nv_bfloat16* __restrict__ xl)
{
    int row = blockIdx.x;
    int s = row & (SEQ - 1);
    int t = tokens[row];
    const float4* e = (const float4*)(emb + (long)t * DMODEL);
    const float4* p = (const float4*)(pos + (long)s * DMODEL);
    for (int d = threadIdx.x; d < DMODEL / 4; d += blockDim.x) {
        float4 a = e[d], b = p[d];
        a.x += b.x; a.y += b.y; a.z += b.z; a.w += b.w;
        *(float4*)&x[(long)row * DMODEL + d * 4] = a;
        __nv_bfloat16 h0, h1, h2, h3, l0, l1, l2, l3;
        split_bf16(a.x, h0, l0); split_bf16(a.y, h1, l1);
        split_bf16(a.z, h2, l2); split_bf16(a.w, h3, l3);
        __nv_bfloat162 hh01; hh01.x = h0; hh01.y = h1;
        __nv_bfloat162 hh23; hh23.x = h2; hh23.y = h3;
        __nv_bfloat162 ll01; ll01.x = l0; ll01.y = l1;
        __nv_bfloat162 ll23; ll23.x = l2; ll23.y = l3;
        long o = (long)row * DMODEL + d * 4;
        *(__nv_bfloat162*)&xh[o] = hh01; *(__nv_bfloat162*)&xh[o + 2] = hh23;
        *(__nv_bfloat162*)&xl[o] = ll01; *(__nv_bfloat162*)&xl[o + 2] = ll23;
    }
}

// ---------------------------------------------------------------------------
// Transpose + split weights: W [K,N] fp32 -> Oh/Ol [N,K] bf16
// ---------------------------------------------------------------------------
__global__ void tconv_kernel(const float* __restrict__ W,
                             __nv_bfloat16* __restrict__ Oh,
                             __nv_bfloat16* __restrict__ Ol,
                             int Kd, int Nd)
{
    __shared__ float ts[32][33];
    int n0 = blockIdx.x * 32, k0 = blockIdx.y * 32;
    for (int i = threadIdx.y; i < 32; i += 8)
        ts[i][threadIdx.x] = W[(long)(k0 + i) * Nd + n0 + threadIdx.x];
    __syncthreads();
    for (int i = threadIdx.y; i < 32; i += 8) {
        float v = ts[threadIdx.x][i];     // = W[k0+tx][n0+i]
        __nv_bfloat16 h, l;
        split_bf16(v, h, l);
        long o = (long)(n0 + i) * Kd + k0 + threadIdx.x;
        Oh[o] = h; Ol[o] = l;
    }
}

// qkv bias concat
__global__ void bias_concat_kernel(const float* __restrict__ bq, const float* __restrict__ bk,
                                   const float* __restrict__ bv, float* __restrict__ out)
{
    int i = blockIdx.x * blockDim.x + threadIdx.x;
    if (i >= NLAYER * QKVN) return;
    int l = i / QKVN, c = i - l * QKVN;
    float v = (c < 1024) ? bq[l * 1024 + c]
            : (c < 2048) ? bk[l * 1024 + c - 1024]
                         : bv[l * 1024 + c - 2048];
    out[i] = v;
}

// ---------------------------------------------------------------------------
// HMMA GEMM: C[M,N] = A[M,K] @ B^T  (B stored [N,K] K-major, bf16 hi/lo)
// 3-pass split: D = Ah*Bh + Ah*Bl + Al*Bh, fp32 accum in registers.
// CTA 128x128, BK=32, 8 warps (2x4), warp tile 64x32, mma.sync m16n8k16.
// SMEM per stage: 4 tiles of [128][32+8pad] bf16 = 40960B; 2 stages.
// ---------------------------------------------------------------------------
#define GSTRIDE 80                  // bytes per smem row (40 bf16)
#define TILE_B  10240               // one [128][40] bf16 tile
#define STAGE_B 40960
#define GEMM_SMEM (2 * STAGE_B)     // 81920

template<bool RELU, bool RESID, bool WF32, bool WBF>
__global__ __launch_bounds__(256)
void hmma_gemm(const __nv_bfloat16* __restrict__ Ah, const __nv_bfloat16* __restrict__ Al,
               const __nv_bfloat16* __restrict__ Bh, const __nv_bfloat16* __restrict__ Bl,
               const float* __restrict__ bias, const float* __restrict__ resid,
               float* __restrict__ Cf, __nv_bfloat16* __restrict__ Chi,
               __nv_bfloat16* __restrict__ Clo, int N, int K)
{
    extern __shared__ char smem[];
    uint32_t sbase = smem_u32(smem);

    int tid = threadIdx.x;
    int lane = tid & 31;
    int wid = tid >> 5;
    int wm = wid & 1;          // 2 warps over M (64 rows each)
    int wn = wid >> 1;         // 4 warps over N (32 cols each)
    int row0 = blockIdx.x * 128;
    int ncol0 = blockIdx.y * 128;
    int nk = K >> 5;

    float c[4][4][4];
#pragma unroll
    for (int i = 0; i < 4; i++)
#pragma unroll
        for (int j = 0; j < 4; j++)
#pragma unroll
            for (int k = 0; k < 4; k++) c[i][j][k] = 0.f;

    auto load_stage = [&](int chunk, int buf) {
        uint32_t sb = sbase + buf * STAGE_B;
        int kc = chunk << 5;
#pragma unroll 2
        for (int i = tid; i < 512; i += 256) {
            int r = i >> 2, cc = i & 3;
            uint32_t d = sb + (uint32_t)(r * GSTRIDE + cc * 16);
            long ga = (long)(row0 + r) * K + kc + cc * 8;
            long gb = (long)(ncol0 + r) * K + kc + cc * 8;
            cp_async16(d,               Ah + ga);
            cp_async16(d + TILE_B,      Al + ga);
            cp_async16(d + 2 * TILE_B,  Bh + gb);
            cp_async16(d + 3 * TILE_B,  Bl + gb);
        }
        cp_commit();
    };

    load_stage(0, 0);

    int arow = (lane & 7) + ((lane >> 3) & 1) * 8;   // ldmatrix row within 16
    int akk = ((lane >> 4) & 1) * 8;                 // ldmatrix k-half select

    for (int ch = 0; ch < nk; ch++) {
        int buf = ch & 1;
        if (ch + 1 < nk) { load_stage(ch + 1, buf ^ 1); cp_wait<1>(); }
        else             { cp_wait<0>(); }
        __syncthreads();

        uint32_t sb = sbase + buf * STAGE_B;
#pragma unroll
        for (int ks = 0; ks < 2; ks++) {
            int k0 = ks * 16;
            uint32_t a_h[4][4], a_l[4][4], b_h[4][2], b_l[4][2];
#pragma unroll
            for (int mi = 0; mi < 4; mi++) {
                uint32_t ad = sb + (uint32_t)((wm * 64 + mi * 16 + arow) * GSTRIDE
                                              + (k0 + akk) * 2);
                ldsm_x4(a_h[mi], ad);
                ldsm_x4(a_l[mi], ad + TILE_B);
            }
#pragma unroll
            for (int p = 0; p < 2; p++) {
                uint32_t bd = sb + 2 * TILE_B
                            + (uint32_t)((wn * 32 + p * 16 + arow) * GSTRIDE
                                         + (k0 + akk) * 2);
                uint32_t r[4];
                ldsm_x4(r, bd);
                b_h[2 * p][0] = r[0]; b_h[2 * p + 1][0] = r[1];
                b_h[2 * p][1] = r[2]; b_h[2 * p + 1][1] = r[3];
                ldsm_x4(r, bd + TILE_B);
                b_l[2 * p][0] = r[0]; b_l[2 * p + 1][0] = r[1];
                b_l[2 * p][1] = r[2]; b_l[2 * p + 1][1] = r[3];
            }
#pragma unroll
            for (int mi = 0; mi < 4; mi++)
#pragma unroll
                for (int ni = 0; ni < 4; ni++) {
                    mma_bf16(c[mi][ni], a_h[mi], b_h[ni]);
                    mma_bf16(c[mi][ni], a_h[mi], b_l[ni]);
                    mma_bf16(c[mi][ni], a_l[mi], b_h[ni]);
                }
        }
        __syncthreads();
    }

    // Epilogue: fragment (mi,ni): rows = wm*64+mi*16+lane/4 (+8), cols = wn*32+ni*8+(lane%4)*2
    int rbase = row0 + wm * 64 + (lane >> 2);
    int cbase = ncol0 + wn * 32 + (lane & 3) * 2;
#pragma unroll
    for (int mi = 0; mi < 4; mi++) {
#pragma unroll
        for (int ni = 0; ni < 4; ni++) {
            int gc = cbase + ni * 8;
            float b0 = __ldg(&bias[gc]), b1 = __ldg(&bias[gc + 1]);
#pragma unroll
            for (int half = 0; half < 2; half++) {
                long gr = rbase + mi * 16 + half * 8;
                float v0 = c[mi][ni][half * 2 + 0] + b0;
                float v1 = c[mi][ni][half * 2 + 1] + b1;
                if (RELU) { v0 = fmaxf(v0, 0.f); v1 = fmaxf(v1, 0.f); }
                if (RESID) {
                    float2 rr = *(const float2*)&resid[gr * N + gc];
                    v0 += rr.x; v1 += rr.y;
                }
                if (WF32) {
                    float2 o; o.x = v0; o.y = v1;
                    *(float2*)&Cf[gr * N + gc] = o;
                }
                if (WBF) {
                    __nv_bfloat16 h0, h1, l0, l1;
                    split_bf16(v0, h0, l0); split_bf16(v1, h1, l1);
                    __nv_bfloat162 hh; hh.x = h0; hh.y = h1;
                    __nv_bfloat162 ll; ll.x = l0; ll.y = l1;
                    *(__nv_bfloat162*)&Chi[gr * N + gc] = hh;
                    *(__nv_bfloat162*)&Clo[gr * N + gc] = ll;
                }
            }
        }
    }
}

// ---------------------------------------------------------------------------
// Flash attention (fp32), reads fused qkv [M,3072], writes a_hi/a_lo bf16
// ---------------------------------------------------------------------------
#define FPAD 68

__global__ __launch_bounds__(256)
void flash_attn_kernel(const float* __restrict__ QKV,
                       __nv_bfloat16* __restrict__ Ahi,
                       __nv_bfloat16* __restrict__ Alo)
{
    extern __shared__ float sm[];
    float* Qs = sm;
    float* Ks = sm + 64 * FPAD;
    float* Vs = sm + 2 * 64 * FPAD;
    float* Ps = sm + 3 * 64 * FPAD;

    int qt = gridDim.x - 1 - blockIdx.x;
    int bh = blockIdx.y;
    int b = bh >> 4;
    int h = bh & 15;
    int tid = threadIdx.x;
    int tx = tid & 15;
    int ty = tid >> 4;

    long baseq = (long)b * SEQ * QKVN + h * HDIM;
    long basek = baseq + 1024;
    long basev = baseq + 2048;

    for (int i = tid; i < 64 * 16; i += 256) {
        int r = i >> 4, c4 = (i & 15) * 4;
        *(float4*)&Qs[r * FPAD + c4] =
            *(const float4*)&QKV[baseq + (long)(qt * 64 + r) * QKVN + c4];
    }

    float m[4], l[4], o[4][4];
#pragma unroll
    for (int i = 0; i < 4; i++) {
        m[i] = -1e30f; l[i] = 0.f;
#pragma unroll
        for (int j = 0; j < 4; j++) o[i][j] = 0.f;
    }

    for (int jt = 0; jt <= qt; jt++) {
        for (int i = tid; i < 64 * 16; i += 256) {
            int r = i >> 4, c4 = (i & 15) * 4;
            long off = (long)(jt * 64 + r) * QKVN + c4;
            *(float4*)&Ks[r * FPAD + c4] = *(const float4*)&QKV[basek + off];
            *(float4*)&Vs[r * FPAD + c4] = *(const float4*)&QKV[basev + off];
        }
        __syncthreads();

        float s[4][4];
#pragma unroll
        for (int i = 0; i < 4; i++)
#pragma unroll
            for (int j = 0; j < 4; j++) s[i][j] = 0.f;

#pragma unroll 4
        for (int k4 = 0; k4 < HDIM; k4 += 4) {
            float4 qv[4], kv[4];
#pragma unroll
            for (int i = 0; i < 4; i++)
                qv[i] = *(const float4*)&Qs[(ty * 4 + i) * FPAD + k4];
#pragma unroll
            for (int j = 0; j < 4; j++)
                kv[j] = *(const float4*)&Ks[(tx + 16 * j) * FPAD + k4];
#pragma unroll
            for (int i = 0; i < 4; i++)
#pragma unroll
                for (int j = 0; j < 4; j++) {
                    s[i][j] = fmaf(qv[i].x, kv[j].x, s[i][j]);
                    s[i][j] = fmaf(qv[i].y, kv[j].y, s[i][j]);
                    s[i][j] = fmaf(qv[i].z, kv[j].z, s[i][j]);
                    s[i][j] = fmaf(qv[i].w, kv[j].w, s[i][j]);
                }
        }

        if (jt == qt) {
#pragma unroll
            for (int i = 0; i < 4; i++) {
                int qloc = ty * 4 + i;
#pragma unroll
                for (int j = 0; j < 4; j++) {
                    int kloc = tx + 16 * j;
                    s[i][j] = (kloc > qloc) ? -1e30f : s[i][j] * 0.125f;
                }
            }
        } else {
#pragma unroll
            for (int i = 0; i < 4; i++)
#pragma unroll
                for (int j = 0; j < 4; j++) s[i][j] *= 0.125f;
        }

#pragma unroll
        for (int i = 0; i < 4; i++) {
            float rmax = fmaxf(fmaxf(s[i][0], s[i][1]), fmaxf(s[i][2], s[i][3]));
#pragma unroll
            for (int w = 1; w < 16; w <<= 1)
                rmax = fmaxf(rmax, __shfl_xor_sync(0xffffffffu, rmax, w));
            float mn = fmaxf(m[i], rmax);
            float corr = __expf(m[i] - mn);
            float rsum = 0.f;
#pragma unroll
            for (int j = 0; j < 4; j++) {
                float p = __expf(s[i][j] - mn);
                s[i][j] = p;
                rsum += p;
            }
#pragma unroll
            for (int w = 1; w < 16; w <<= 1)
                rsum += __shfl_xor_sync(0xffffffffu, rsum, w);
            l[i] = l[i] * corr + rsum;
            m[i] = mn;
#pragma unroll
            for (int j = 0; j < 4; j++) o[i][j] *= corr;
        }

#pragma unroll
        for (int i = 0; i < 4; i++)
#pragma unroll
            for (int j = 0; j < 4; j++)
                Ps[(ty * 4 + i) * FPAD + tx + 16 * j] = s[i][j];
        __syncthreads();

#pragma unroll 4
        for (int k4 = 0; k4 < 64; k4 += 4) {
            float4 pv[4];
#pragma unroll
            for (int i = 0; i < 4; i++)
                pv[i] = *(const float4*)&Ps[(ty * 4 + i) * FPAD + k4];
#pragma unroll
            for (int cc = 0; cc < 4; cc++) {
                float4 vv = *(const float4*)&Vs[(k4 + cc) * FPAD + tx * 4];
#pragma unroll
                for (int i = 0; i < 4; i++) {
                    float p = (cc == 0) ? pv[i].x : (cc == 1) ? pv[i].y
                              : (cc == 2) ? pv[i].z : pv[i].w;
                    o[i][0] = fmaf(p, vv.x, o[i][0]);
                    o[i][1] = fmaf(p, vv.y, o[i][1]);
                    o[i][2] = fmaf(p, vv.z, o[i][2]);
                    o[i][3] = fmaf(p, vv.w, o[i][3]);
                }
            }
        }
        __syncthreads();
    }

#pragma unroll
    for (int i = 0; i < 4; i++) {
        float inv = 1.0f / l[i];
        int qg = qt * 64 + ty * 4 + i;
        float v0 = o[i][0] * inv, v1 = o[i][1] * inv;
        float v2 = o[i][2] * inv, v3 = o[i][3] * inv;
        __nv_bfloat16 h0, h1, h2, h3, l0, l1, l2, l3;
        split_bf16(v0, h0, l0); split_bf16(v1, h1, l1);
        split_bf16(v2, h2, l2); split_bf16(v3, h3, l3);
        __nv_bfloat162 hh01; hh01.x = h0; hh01.y = h1;
        __nv_bfloat162 hh23; hh23.x = h2; hh23.y = h3;
        __nv_bfloat162 ll01; ll01.x = l0; ll01.y = l1;
        __nv_bfloat162 ll23; ll23.x = l2; ll23.y = l3;
        long oaddr = (long)(b * SEQ + qg) * HK + h * HDIM + tx * 4;
        *(__nv_bfloat162*)&Ahi[oaddr] = hh01; *(__nv_bfloat162*)&Ahi[oaddr + 2] = hh23;
        *(__nv_bfloat162*)&Alo[oaddr] = ll01; *(__nv_bfloat162*)&Alo[oaddr + 2] = ll23;
    }
}

#define FLASH_SMEM (4 * 64 * FPAD * 4)

// ---------------------------------------------------------------------------
// Launch
// ---------------------------------------------------------------------------
extern "C" void kernel_launch(void* const* d_in, const int* in_sizes, int n_in,
                              void* d_out, int out_size)
{
    const int*   tokens = (const int*)  d_in[0];
    const float* emb    = (const float*)d_in[1];
    const float* pos    = (const float*)d_in[2];
    const float* Wq     = (const float*)d_in[3];
    const float* bq     = (const float*)d_in[4];
    const float* Wk     = (const float*)d_in[5];
    const float* bk     = (const float*)d_in[6];
    const float* Wv     = (const float*)d_in[7];
    const float* bv     = (const float*)d_in[8];
    const float* Wo     = (const float*)d_in[9];
    const float* bo     = (const float*)d_in[10];
    const float* W1     = (const float*)d_in[11];
    const float* b1     = (const float*)d_in[12];
    const float* W2     = (const float*)d_in[13];
    const float* b2     = (const float*)d_in[14];
    const float* Wf     = (const float*)d_in[15];
    const float* bf     = (const float*)d_in[16];
    float* out = (float*)d_out;

    float *x, *qkv, *qkvb;
    __nv_bfloat16 *xh, *xl, *ah, *al, *fh, *fl;
    __nv_bfloat16 *wqkvh, *wqkvl, *woh, *wol, *w1h, *w1l, *w2h, *w2l, *wfh, *wfl;
    cudaGetSymbolAddress((void**)&x, g_x);
    cudaGetSymbolAddress((void**)&qkv, g_qkv);
    cudaGetSymbolAddress((void**)&qkvb, g_qkvb);
    cudaGetSymbolAddress((void**)&xh, g_xh);   cudaGetSymbolAddress((void**)&xl, g_xl);
    cudaGetSymbolAddress((void**)&ah, g_ah);   cudaGetSymbolAddress((void**)&al, g_al);
    cudaGetSymbolAddress((void**)&fh, g_fh);   cudaGetSymbolAddress((void**)&fl, g_fl);
    cudaGetSymbolAddress((void**)&wqkvh, g_wqkvh); cudaGetSymbolAddress((void**)&wqkvl, g_wqkvl);
    cudaGetSymbolAddress((void**)&woh, g_woh); cudaGetSymbolAddress((void**)&wol, g_wol);
    cudaGetSymbolAddress((void**)&w1h, g_w1h); cudaGetSymbolAddress((void**)&w1l, g_w1l);
    cudaGetSymbolAddress((void**)&w2h, g_w2h); cudaGetSymbolAddress((void**)&w2l, g_w2l);
    cudaGetSymbolAddress((void**)&wfh, g_wfh); cudaGetSymbolAddress((void**)&wfl, g_wfl);

    static bool attr_set = false;
    if (!attr_set) {
        cudaFuncSetAttribute(flash_attn_kernel,
                             cudaFuncAttributeMaxDynamicSharedMemorySize, FLASH_SMEM);
        cudaFuncSetAttribute(hmma_gemm<false, false, true, false>,
                             cudaFuncAttributeMaxDynamicSharedMemorySize, GEMM_SMEM);
        cudaFuncSetAttribute(hmma_gemm<false, true, true, true>,
                             cudaFuncAttributeMaxDynamicSharedMemorySize, GEMM_SMEM);
        cudaFuncSetAttribute(hmma_gemm<true, false, false, true>,
                             cudaFuncAttributeMaxDynamicSharedMemorySize, GEMM_SMEM);
        attr_set = true;
    }

    dim3 tb(32, 8);

    // ---- weight conversion (transpose + bf16 hi/lo split) ----
    for (int l = 0; l < NLAYER; l++) {
        tconv_kernel<<<dim3(HK / 32, DMODEL / 32), tb>>>(
            Wq + (long)l * DMODEL * HK, wqkvh + ((long)l * QKVN + 0) * DMODEL,
            wqkvl + ((long)l * QKVN + 0) * DMODEL, DMODEL, HK);
        tconv_kernel<<<dim3(HK / 32, DMODEL / 32), tb>>>(
            Wk + (long)l * DMODEL * HK, wqkvh + ((long)l * QKVN + 1024) * DMODEL,
            wqkvl + ((long)l * QKVN + 1024) * DMODEL, DMODEL, HK);
        tconv_kernel<<<dim3(HK / 32, DMODEL / 32), tb>>>(
            Wv + (long)l * DMODEL * HK, wqkvh + ((long)l * QKVN + 2048) * DMODEL,
            wqkvl + ((long)l * QKVN + 2048) * DMODEL, DMODEL, HK);
        tconv_kernel<<<dim3(DMODEL / 32, HK / 32), tb>>>(
            Wo + (long)l * HK * DMODEL, woh + (long)l * DMODEL * HK,
            wol + (long)l * DMODEL * HK, HK, DMODEL);
        tconv_kernel<<<dim3(FFDIM / 32, DMODEL / 32), tb>>>(
            W1 + (long)l * DMODEL * FFDIM, w1h + (long)l * FFDIM * DMODEL,
            w1l + (long)l * FFDIM * DMODEL, DMODEL, FFDIM);
        tconv_kernel<<<dim3(DMODEL / 32, FFDIM / 32), tb>>>(
            W2 + (long)l * FFDIM * DMODEL, w2h + (long)l * DMODEL * FFDIM,
            w2l + (long)l * DMODEL * FFDIM, FFDIM, DMODEL);
    }
    tconv_kernel<<<dim3(VOCAB / 32, DMODEL / 32), tb>>>(Wf, wfh, wfl, DMODEL, VOCAB);
    bias_concat_kernel<<<(NLAYER * QKVN + 255) / 256, 256>>>(bq, bk, bv, qkvb);

    // ---- forward ----
    embed_kernel<<<MTOK, 256>>>(tokens, emb, pos, x, xh, xl);

    dim3 gQKV(MTOK / 128, QKVN / 128);
    dim3 gProj(MTOK / 128, DMODEL / 128);
    dim3 gFF1(MTOK / 128, FFDIM / 128);
    dim3 gLogits(MTOK / 128, VOCAB / 128);
    dim3 gAttn(SEQ / 64, BATCH * NHEAD);

    for (int l = 0; l < NLAYER; l++) {
        const __nv_bfloat16* wqh = wqkvh + (long)l * QKVN * DMODEL;
        const __nv_bfloat16* wql = wqkvl + (long)l * QKVN * DMODEL;

        // qkv = x @ Wqkv + b  (fp32 out)
        hmma_gemm<false, false, true, false><<<gQKV, 256, GEMM_SMEM>>>(
            xh, xl, wqh, wql, qkvb + (long)l * QKVN, nullptr,
            qkv, nullptr, nullptr, QKVN, DMODEL);

        flash_attn_kernel<<<gAttn, 256, FLASH_SMEM>>>(qkv, ah, al);

        // x = x + a @ Wo + bo  (fp32 + hi/lo out)
        hmma_gemm<false, true, true, true><<<gProj, 256, GEMM_SMEM>>>(
            ah, al, woh + (long)l * DMODEL * HK, wol + (long)l * DMODEL * HK,
            bo + (long)l * DMODEL, x, x, xh, xl, DMODEL, HK);

        // f = relu(x @ W1 + b1)  (hi/lo only)
        hmma_gemm<true, false, false, true><<<gFF1, 256, GEMM_SMEM>>>(
            xh, xl, w1h + (long)l * FFDIM * DMODEL, w1l + (long)l * FFDIM * DMODEL,
            b1 + (long)l * FFDIM, nullptr, nullptr, fh, fl, FFDIM, DMODEL);

        // x = x + f @ W2 + b2
        hmma_gemm<false, true, true, true><<<gProj, 256, GEMM_SMEM>>>(
            fh, fl, w2h + (long)l * DMODEL * FFDIM, w2l + (long)l * DMODEL * FFDIM,
            b2 + (long)l * DMODEL, x, x, xh, xl, DMODEL, FFDIM);
    }

    // logits = x @ Wf + bf
    hmma_gemm<false, false, true, false><<<gLogits, 256, GEMM_SMEM>>>(
        xh, xl, wfh, wfl, bf, nullptr, out, nullptr, nullptr, VOCAB, DMODEL);
}

// round 5
// speedup vs baseline: 10.6280x; 1.3122x over previous
#include <cuda_runtime.h>
#include <cuda_fp16.h>
#include <cstdint>

// Problem constants
#define VOCAB 32000
#define DMODEL 1024
#define NHEAD 16
#define HDIM 64
#define FFDIM 4096
#define NLAYER 4
#define SEQ 2048
#define BATCH 2
#define MTOK (BATCH * SEQ)      // 4096 token rows
#define HK (NHEAD * HDIM)       // 1024
#define QKVN 3072               // fused q|k|v output width

// ---------------------------------------------------------------------------
// Scratch (device globals; no allocations allowed)
// ---------------------------------------------------------------------------
__device__ float g_x[MTOK * DMODEL];                 // residual stream fp32
__device__ float g_qkv[MTOK * QKVN];                 // fused qkv fp32
__device__ float g_qkvb[NLAYER * QKVN];              // fused qkv bias
__device__ __half g_xh[MTOK * DMODEL];               // activations fp16
__device__ __half g_ah[MTOK * HK];
__device__ __half g_fh[MTOK * FFDIM];
// transposed fp16 weights [N,K] hi/lo
__device__ __half g_wqkvh[NLAYER * QKVN * DMODEL], g_wqkvl[NLAYER * QKVN * DMODEL];
__device__ __half g_woh[NLAYER * DMODEL * HK],     g_wol[NLAYER * DMODEL * HK];
__device__ __half g_w1h[NLAYER * FFDIM * DMODEL],  g_w1l[NLAYER * FFDIM * DMODEL];
__device__ __half g_w2h[NLAYER * DMODEL * FFDIM],  g_w2l[NLAYER * DMODEL * FFDIM];
__device__ __half g_wfh[VOCAB * DMODEL],           g_wfl[VOCAB * DMODEL];

// ---------------------------------------------------------------------------
// PTX helpers (all sm_80-era, arch-portable)
// ---------------------------------------------------------------------------
__device__ __forceinline__ uint32_t smem_u32(const void* p) {
    return (uint32_t)__cvta_generic_to_shared(p);
}
__device__ __forceinline__ void cp_async16(uint32_t dst, const void* src) {
    asm volatile("cp.async.cg.shared.global [%0], [%1], 16;\n" :: "r"(dst), "l"(src));
}
__device__ __forceinline__ void cp_commit() { asm volatile("cp.async.commit_group;\n" ::: "memory"); }
template<int N> __device__ __forceinline__ void cp_wait() {
    asm volatile("cp.async.wait_group %0;\n" :: "n"(N) : "memory");
}
__device__ __forceinline__ void ldsm_x4(uint32_t* r, uint32_t addr) {
    asm volatile("ldmatrix.sync.aligned.m8n8.x4.shared.b16 {%0,%1,%2,%3}, [%4];"
                 : "=r"(r[0]), "=r"(r[1]), "=r"(r[2]), "=r"(r[3]) : "r"(addr));
}
__device__ __forceinline__ void mma_f16(float* c, const uint32_t* a, const uint32_t* b) {
    asm volatile(
        "mma.sync.aligned.m16n8k16.row.col.f32.f16.f16.f32 "
        "{%0,%1,%2,%3}, {%4,%5,%6,%7}, {%8,%9}, {%0,%1,%2,%3};"
        : "+f"(c[0]), "+f"(c[1]), "+f"(c[2]), "+f"(c[3])
        : "r"(a[0]), "r"(a[1]), "r"(a[2]), "r"(a[3]), "r"(b[0]), "r"(b[1]));
}

// ---------------------------------------------------------------------------
// fp16 hi/lo split helper
// ---------------------------------------------------------------------------
__device__ __forceinline__ void split_half(float v, __half& h, __half& l) {
    h = __float2half_rn(v);
    l = __float2half_rn(v - __half2float(h));
}

// ---------------------------------------------------------------------------
// Embedding: x = emb[token] + pos ; also writes fp16
// ---------------------------------------------------------------------------
__global__ void embed_kernel(const int* __restrict__ tokens,
                             const float* __restrict__ emb,
                             const float* __restrict__ pos,
                             float* __restrict__ x,
                             __half* __restrict__ xh)
{
    int row = blockIdx.x;
    int s = row & (SEQ - 1);
    int t = tokens[row];
    const float4* e = (const float4*)(emb + (long)t * DMODEL);
    const float4* p = (const float4*)(pos + (long)s * DMODEL);
    for (int d = threadIdx.x; d < DMODEL / 4; d += blockDim.x) {
        float4 a = e[d], b = p[d];
        a.x += b.x; a.y += b.y; a.z += b.z; a.w += b.w;
        long o = (long)row * DMODEL + d * 4;
        *(float4*)&x[o] = a;
        __half2 h01, h23;
        h01.x = __float2half_rn(a.x); h01.y = __float2half_rn(a.y);
        h23.x = __float2half_rn(a.z); h23.y = __float2half_rn(a.w);
        *(__half2*)&xh[o] = h01; *(__half2*)&xh[o + 2] = h23;
    }
}

// ---------------------------------------------------------------------------
// Transpose + split weights: W [K,N] fp32 -> Oh/Ol [N,K] fp16
// ---------------------------------------------------------------------------
__global__ void tconv_kernel(const float* __restrict__ W,
                             __half* __restrict__ Oh,
                             __half* __restrict__ Ol,
                             int Kd, int Nd)
{
    __shared__ float ts[32][33];
    int n0 = blockIdx.x * 32, k0 = blockIdx.y * 32;
    for (int i = threadIdx.y; i < 32; i += 8)
        ts[i][threadIdx.x] = W[(long)(k0 + i) * Nd + n0 + threadIdx.x];
    __syncthreads();
    for (int i = threadIdx.y; i < 32; i += 8) {
        float v = ts[threadIdx.x][i];     // = W[k0+tx][n0+i]
        __half h, l;
        split_half(v, h, l);
        long o = (long)(n0 + i) * Kd + k0 + threadIdx.x;
        Oh[o] = h; Ol[o] = l;
    }
}

// qkv bias concat
__global__ void bias_concat_kernel(const float* __restrict__ bq, const float* __restrict__ bk,
                                   const float* __restrict__ bv, float* __restrict__ out)
{
    int i = blockIdx.x * blockDim.x + threadIdx.x;
    if (i >= NLAYER * QKVN) return;
    int l = i / QKVN, c = i - l * QKVN;
    float v = (c < 1024) ? bq[l * 1024 + c]
            : (c < 2048) ? bk[l * 1024 + c - 1024]
                         : bv[l * 1024 + c - 2048];
    out[i] = v;
}

// ---------------------------------------------------------------------------
// HMMA GEMM: C[M,N] = A[M,K] @ B^T  (A fp16, B stored [N,K] K-major fp16 hi/lo)
// 2-pass split: D = A*Bh + A*Bl, fp32 accum in registers.
// CTA 128x128, BK=32, 8 warps (2x4), warp tile 64x32, mma.sync m16n8k16.
// 3-stage cp.async pipeline, one __syncthreads per k-chunk.
// ---------------------------------------------------------------------------
#define GSTRIDE 80                  // bytes per smem row (40 halves)
#define TILE_B  10240               // one [128][40] fp16 tile
#define STAGE_B 30720               // A + Bh + Bl
#define GEMM_SMEM (3 * STAGE_B)     // 92160

template<bool RELU, bool RESID, bool WF32, bool WH16>
__global__ __launch_bounds__(256)
void hmma_gemm(const __half* __restrict__ A,
               const __half* __restrict__ Bh, const __half* __restrict__ Bl,
               const float* __restrict__ bias, const float* __restrict__ resid,
               float* __restrict__ Cf, __half* __restrict__ Ch,
               int N, int K)
{
    extern __shared__ char smem[];
    uint32_t sbase = smem_u32(smem);

    int tid = threadIdx.x;
    int lane = tid & 31;
    int wid = tid >> 5;
    int wm = wid & 1;          // 2 warps over M (64 rows each)
    int wn = wid >> 1;         // 4 warps over N (32 cols each)
    int row0 = blockIdx.x * 128;
    int ncol0 = blockIdx.y * 128;
    int nk = K >> 5;           // >= 32 always here

    float c[4][4][4];
#pragma unroll
    for (int i = 0; i < 4; i++)
#pragma unroll
        for (int j = 0; j < 4; j++)
#pragma unroll
            for (int k = 0; k < 4; k++) c[i][j][k] = 0.f;

    auto load_stage = [&](int chunk, int buf) {
        uint32_t sb = sbase + buf * STAGE_B;
        int kc = chunk << 5;
#pragma unroll 2
        for (int i = tid; i < 512; i += 256) {
            int r = i >> 2, cc = i & 3;
            uint32_t d = sb + (uint32_t)(r * GSTRIDE + cc * 16);
            long ga = (long)(row0 + r) * K + kc + cc * 8;
            long gb = (long)(ncol0 + r) * K + kc + cc * 8;
            cp_async16(d,              A + ga);
            cp_async16(d + TILE_B,     Bh + gb);
            cp_async16(d + 2 * TILE_B, Bl + gb);
        }
        cp_commit();
    };

    load_stage(0, 0);
    load_stage(1, 1);

    int arow = (lane & 7) + ((lane >> 3) & 1) * 8;   // ldmatrix row within 16
    int akk = ((lane >> 4) & 1) * 8;                 // ldmatrix k-half select

    for (int ch = 0; ch < nk; ch++) {
        int buf = ch % 3;
        if (ch + 1 < nk) cp_wait<1>(); else cp_wait<0>();
        __syncthreads();
        if (ch + 2 < nk) load_stage(ch + 2, (ch + 2) % 3);

        uint32_t sb = sbase + buf * STAGE_B;
#pragma unroll
        for (int ks = 0; ks < 2; ks++) {
            int k0 = ks * 16;
            uint32_t a_r[4][4], b_h[4][2], b_l[4][2];
#pragma unroll
            for (int mi = 0; mi < 4; mi++) {
                uint32_t ad = sb + (uint32_t)((wm * 64 + mi * 16 + arow) * GSTRIDE
                                              + (k0 + akk) * 2);
                ldsm_x4(a_r[mi], ad);
            }
#pragma unroll
            for (int p = 0; p < 2; p++) {
                uint32_t bd = sb + TILE_B
                            + (uint32_t)((wn * 32 + p * 16 + arow) * GSTRIDE
                                         + (k0 + akk) * 2);
                uint32_t r[4];
                ldsm_x4(r, bd);
                b_h[2 * p][0] = r[0]; b_h[2 * p + 1][0] = r[1];
                b_h[2 * p][1] = r[2]; b_h[2 * p + 1][1] = r[3];
                ldsm_x4(r, bd + TILE_B);
                b_l[2 * p][0] = r[0]; b_l[2 * p + 1][0] = r[1];
                b_l[2 * p][1] = r[2]; b_l[2 * p + 1][1] = r[3];
            }
#pragma unroll
            for (int mi = 0; mi < 4; mi++)
#pragma unroll
                for (int ni = 0; ni < 4; ni++) {
                    mma_f16(c[mi][ni], a_r[mi], b_h[ni]);
                    mma_f16(c[mi][ni], a_r[mi], b_l[ni]);
                }
        }
    }

    // Epilogue: fragment (mi,ni): rows = wm*64+mi*16+lane/4 (+8), cols = wn*32+ni*8+(lane%4)*2
    int rbase = row0 + wm * 64 + (lane >> 2);
    int cbase = ncol0 + wn * 32 + (lane & 3) * 2;
#pragma unroll
    for (int mi = 0; mi < 4; mi++) {
#pragma unroll
        for (int ni = 0; ni < 4; ni++) {
            int gc = cbase + ni * 8;
            float b0 = __ldg(&bias[gc]), b1 = __ldg(&bias[gc + 1]);
#pragma unroll
            for (int half_ = 0; half_ < 2; half_++) {
                long gr = rbase + mi * 16 + half_ * 8;
                float v0 = c[mi][ni][half_ * 2 + 0] + b0;
                float v1 = c[mi][ni][half_ * 2 + 1] + b1;
                if (RELU) { v0 = fmaxf(v0, 0.f); v1 = fmaxf(v1, 0.f); }
                if (RESID) {
                    float2 rr = *(const float2*)&resid[gr * N + gc];
                    v0 += rr.x; v1 += rr.y;
                }
                if (WF32) {
                    float2 o; o.x = v0; o.y = v1;
                    *(float2*)&Cf[gr * N + gc] = o;
                }
                if (WH16) {
                    __half2 hh;
                    hh.x = __float2half_rn(v0); hh.y = __float2half_rn(v1);
                    *(__half2*)&Ch[gr * N + gc] = hh;
                }
            }
        }
    }
}

// ---------------------------------------------------------------------------
// Flash attention (fp32), reads fused qkv [M,3072], writes fp16 attn out
// ---------------------------------------------------------------------------
#define FPAD 68

__global__ __launch_bounds__(256)
void flash_attn_kernel(const float* __restrict__ QKV,
                       __half* __restrict__ Ao)
{
    extern __shared__ float sm[];
    float* Qs = sm;
    float* Ks = sm + 64 * FPAD;
    float* Vs = sm + 2 * 64 * FPAD;
    float* Ps = sm + 3 * 64 * FPAD;

    int qt = gridDim.x - 1 - blockIdx.x;
    int bh = blockIdx.y;
    int b = bh >> 4;
    int h = bh & 15;
    int tid = threadIdx.x;
    int tx = tid & 15;
    int ty = tid >> 4;

    long baseq = (long)b * SEQ * QKVN + h * HDIM;
    long basek = baseq + 1024;
    long basev = baseq + 2048;

    for (int i = tid; i < 64 * 16; i += 256) {
        int r = i >> 4, c4 = (i & 15) * 4;
        *(float4*)&Qs[r * FPAD + c4] =
            *(const float4*)&QKV[baseq + (long)(qt * 64 + r) * QKVN + c4];
    }

    float m[4], l[4], o[4][4];
#pragma unroll
    for (int i = 0; i < 4; i++) {
        m[i] = -1e30f; l[i] = 0.f;
#pragma unroll
        for (int j = 0; j < 4; j++) o[i][j] = 0.f;
    }

    for (int jt = 0; jt <= qt; jt++) {
        for (int i = tid; i < 64 * 16; i += 256) {
            int r = i >> 4, c4 = (i & 15) * 4;
            long off = (long)(jt * 64 + r) * QKVN + c4;
            *(float4*)&Ks[r * FPAD + c4] = *(const float4*)&QKV[basek + off];
            *(float4*)&Vs[r * FPAD + c4] = *(const float4*)&QKV[basev + off];
        }
        __syncthreads();

        float s[4][4];
#pragma unroll
        for (int i = 0; i < 4; i++)
#pragma unroll
            for (int j = 0; j < 4; j++) s[i][j] = 0.f;

#pragma unroll 4
        for (int k4 = 0; k4 < HDIM; k4 += 4) {
            float4 qv[4], kv[4];
#pragma unroll
            for (int i = 0; i < 4; i++)
                qv[i] = *(const float4*)&Qs[(ty * 4 + i) * FPAD + k4];
#pragma unroll
            for (int j = 0; j < 4; j++)
                kv[j] = *(const float4*)&Ks[(tx + 16 * j) * FPAD + k4];
#pragma unroll
            for (int i = 0; i < 4; i++)
#pragma unroll
                for (int j = 0; j < 4; j++) {
                    s[i][j] = fmaf(qv[i].x, kv[j].x, s[i][j]);
                    s[i][j] = fmaf(qv[i].y, kv[j].y, s[i][j]);
                    s[i][j] = fmaf(qv[i].z, kv[j].z, s[i][j]);
                    s[i][j] = fmaf(qv[i].w, kv[j].w, s[i][j]);
                }
        }

        if (jt == qt) {
#pragma unroll
            for (int i = 0; i < 4; i++) {
                int qloc = ty * 4 + i;
#pragma unroll
                for (int j = 0; j < 4; j++) {
                    int kloc = tx + 16 * j;
                    s[i][j] = (kloc > qloc) ? -1e30f : s[i][j] * 0.125f;
                }
            }
        } else {
#pragma unroll
            for (int i = 0; i < 4; i++)
#pragma unroll
                for (int j = 0; j < 4; j++) s[i][j] *= 0.125f;
        }

#pragma unroll
        for (int i = 0; i < 4; i++) {
            float rmax = fmaxf(fmaxf(s[i][0], s[i][1]), fmaxf(s[i][2], s[i][3]));
#pragma unroll
            for (int w = 1; w < 16; w <<= 1)
                rmax = fmaxf(rmax, __shfl_xor_sync(0xffffffffu, rmax, w));
            float mn = fmaxf(m[i], rmax);
            float corr = __expf(m[i] - mn);
            float rsum = 0.f;
#pragma unroll
            for (int j = 0; j < 4; j++) {
                float p = __expf(s[i][j] - mn);
                s[i][j] = p;
                rsum += p;
            }
#pragma unroll
            for (int w = 1; w < 16; w <<= 1)
                rsum += __shfl_xor_sync(0xffffffffu, rsum, w);
            l[i] = l[i] * corr + rsum;
            m[i] = mn;
#pragma unroll
            for (int j = 0; j < 4; j++) o[i][j] *= corr;
        }

#pragma unroll
        for (int i = 0; i < 4; i++)
#pragma unroll
            for (int j = 0; j < 4; j++)
                Ps[(ty * 4 + i) * FPAD + tx + 16 * j] = s[i][j];
        __syncthreads();

#pragma unroll 4
        for (int k4 = 0; k4 < 64; k4 += 4) {
            float4 pv[4];
#pragma unroll
            for (int i = 0; i < 4; i++)
                pv[i] = *(const float4*)&Ps[(ty * 4 + i) * FPAD + k4];
#pragma unroll
            for (int cc = 0; cc < 4; cc++) {
                float4 vv = *(const float4*)&Vs[(k4 + cc) * FPAD + tx * 4];
#pragma unroll
                for (int i = 0; i < 4; i++) {
                    float p = (cc == 0) ? pv[i].x : (cc == 1) ? pv[i].y
                              : (cc == 2) ? pv[i].z : pv[i].w;
                    o[i][0] = fmaf(p, vv.x, o[i][0]);
                    o[i][1] = fmaf(p, vv.y, o[i][1]);
                    o[i][2] = fmaf(p, vv.z, o[i][2]);
                    o[i][3] = fmaf(p, vv.w, o[i][3]);
                }
            }
        }
        __syncthreads();
    }

#pragma unroll
    for (int i = 0; i < 4; i++) {
        float inv = 1.0f / l[i];
        int qg = qt * 64 + ty * 4 + i;
        __half2 h01, h23;
        h01.x = __float2half_rn(o[i][0] * inv);
        h01.y = __float2half_rn(o[i][1] * inv);
        h23.x = __float2half_rn(o[i][2] * inv);
        h23.y = __float2half_rn(o[i][3] * inv);
        long oaddr = (long)(b * SEQ + qg) * HK + h * HDIM + tx * 4;
        *(__half2*)&Ao[oaddr] = h01; *(__half2*)&Ao[oaddr + 2] = h23;
    }
}

#define FLASH_SMEM (4 * 64 * FPAD * 4)

// ---------------------------------------------------------------------------
// Launch
// ---------------------------------------------------------------------------
extern "C" void kernel_launch(void* const* d_in, const int* in_sizes, int n_in,
                              void* d_out, int out_size)
{
    const int*   tokens = (const int*)  d_in[0];
    const float* emb    = (const float*)d_in[1];
    const float* pos    = (const float*)d_in[2];
    const float* Wq     = (const float*)d_in[3];
    const float* bq     = (const float*)d_in[4];
    const float* Wk     = (const float*)d_in[5];
    const float* bk     = (const float*)d_in[6];
    const float* Wv     = (const float*)d_in[7];
    const float* bv     = (const float*)d_in[8];
    const float* Wo     = (const float*)d_in[9];
    const float* bo     = (const float*)d_in[10];
    const float* W1     = (const float*)d_in[11];
    const float* b1     = (const float*)d_in[12];
    const float* W2     = (const float*)d_in[13];
    const float* b2     = (const float*)d_in[14];
    const float* Wf     = (const float*)d_in[15];
    const float* bf     = (const float*)d_in[16];
    float* out = (float*)d_out;

    float *x, *qkv, *qkvb;
    __half *xh, *ah, *fh;
    __half *wqkvh, *wqkvl, *woh, *wol, *w1h, *w1l, *w2h, *w2l, *wfh, *wfl;
    cudaGetSymbolAddress((void**)&x, g_x);
    cudaGetSymbolAddress((void**)&qkv, g_qkv);
    cudaGetSymbolAddress((void**)&qkvb, g_qkvb);
    cudaGetSymbolAddress((void**)&xh, g_xh);
    cudaGetSymbolAddress((void**)&ah, g_ah);
    cudaGetSymbolAddress((void**)&fh, g_fh);
    cudaGetSymbolAddress((void**)&wqkvh, g_wqkvh); cudaGetSymbolAddress((void**)&wqkvl, g_wqkvl);
    cudaGetSymbolAddress((void**)&woh, g_woh); cudaGetSymbolAddress((void**)&wol, g_wol);
    cudaGetSymbolAddress((void**)&w1h, g_w1h); cudaGetSymbolAddress((void**)&w1l, g_w1l);
    cudaGetSymbolAddress((void**)&w2h, g_w2h); cudaGetSymbolAddress((void**)&w2l, g_w2l);
    cudaGetSymbolAddress((void**)&wfh, g_wfh); cudaGetSymbolAddress((void**)&wfl, g_wfl);

    static bool attr_set = false;
    if (!attr_set) {
        cudaFuncSetAttribute(flash_attn_kernel,
                             cudaFuncAttributeMaxDynamicSharedMemorySize, FLASH_SMEM);
        cudaFuncSetAttribute(hmma_gemm<false, false, true, false>,
                             cudaFuncAttributeMaxDynamicSharedMemorySize, GEMM_SMEM);
        cudaFuncSetAttribute(hmma_gemm<false, true, true, true>,
                             cudaFuncAttributeMaxDynamicSharedMemorySize, GEMM_SMEM);
        cudaFuncSetAttribute(hmma_gemm<true, false, false, true>,
                             cudaFuncAttributeMaxDynamicSharedMemorySize, GEMM_SMEM);
        attr_set = true;
    }

    dim3 tb(32, 8);

    // ---- weight conversion (transpose + fp16 hi/lo split) ----
    for (int l = 0; l < NLAYER; l++) {
        tconv_kernel<<<dim3(HK / 32, DMODEL / 32), tb>>>(
            Wq + (long)l * DMODEL * HK, wqkvh + ((long)l * QKVN + 0) * DMODEL,
            wqkvl + ((long)l * QKVN + 0) * DMODEL, DMODEL, HK);
        tconv_kernel<<<dim3(HK / 32, DMODEL / 32), tb>>>(
            Wk + (long)l * DMODEL * HK, wqkvh + ((long)l * QKVN + 1024) * DMODEL,
            wqkvl + ((long)l * QKVN + 1024) * DMODEL, DMODEL, HK);
        tconv_kernel<<<dim3(HK / 32, DMODEL / 32), tb>>>(
            Wv + (long)l * DMODEL * HK, wqkvh + ((long)l * QKVN + 2048) * DMODEL,
            wqkvl + ((long)l * QKVN + 2048) * DMODEL, DMODEL, HK);
        tconv_kernel<<<dim3(DMODEL / 32, HK / 32), tb>>>(
            Wo + (long)l * HK * DMODEL, woh + (long)l * DMODEL * HK,
            wol + (long)l * DMODEL * HK, HK, DMODEL);
        tconv_kernel<<<dim3(FFDIM / 32, DMODEL / 32), tb>>>(
            W1 + (long)l * DMODEL * FFDIM, w1h + (long)l * FFDIM * DMODEL,
            w1l + (long)l * FFDIM * DMODEL, DMODEL, FFDIM);
        tconv_kernel<<<dim3(DMODEL / 32, FFDIM / 32), tb>>>(
            W2 + (long)l * FFDIM * DMODEL, w2h + (long)l * DMODEL * FFDIM,
            w2l + (long)l * DMODEL * FFDIM, FFDIM, DMODEL);
    }
    tconv_kernel<<<dim3(VOCAB / 32, DMODEL / 32), tb>>>(Wf, wfh, wfl, DMODEL, VOCAB);
    bias_concat_kernel<<<(NLAYER * QKVN + 255) / 256, 256>>>(bq, bk, bv, qkvb);

    // ---- forward ----
    embed_kernel<<<MTOK, 256>>>(tokens, emb, pos, x, xh);

    dim3 gQKV(MTOK / 128, QKVN / 128);
    dim3 gProj(MTOK / 128, DMODEL / 128);
    dim3 gFF1(MTOK / 128, FFDIM / 128);
    dim3 gLogits(MTOK / 128, VOCAB / 128);
    dim3 gAttn(SEQ / 64, BATCH * NHEAD);

    for (int l = 0; l < NLAYER; l++) {
        const __half* wqh = wqkvh + (long)l * QKVN * DMODEL;
        const __half* wql = wqkvl + (long)l * QKVN * DMODEL;

        // qkv = x @ Wqkv + b  (fp32 out)
        hmma_gemm<false, false, true, false><<<gQKV, 256, GEMM_SMEM>>>(
            xh, wqh, wql, qkvb + (long)l * QKVN, nullptr,
            qkv, nullptr, QKVN, DMODEL);

        flash_attn_kernel<<<gAttn, 256, FLASH_SMEM>>>(qkv, ah);

        // x = x + a @ Wo + bo  (fp32 + fp16 out)
        hmma_gemm<false, true, true, true><<<gProj, 256, GEMM_SMEM>>>(
            ah, woh + (long)l * DMODEL * HK, wol + (long)l * DMODEL * HK,
            bo + (long)l * DMODEL, x, x, xh, DMODEL, HK);

        // f = relu(x @ W1 + b1)  (fp16 only)
        hmma_gemm<true, false, false, true><<<gFF1, 256, GEMM_SMEM>>>(
            xh, w1h + (long)l * FFDIM * DMODEL, w1l + (long)l * FFDIM * DMODEL,
            b1 + (long)l * FFDIM, nullptr, nullptr, fh, FFDIM, DMODEL);

        // x = x + f @ W2 + b2
        hmma_gemm<false, true, true, true><<<gProj, 256, GEMM_SMEM>>>(
            fh, w2h + (long)l * DMODEL * FFDIM, w2l + (long)l * DMODEL * FFDIM,
            b2 + (long)l * DMODEL, x, x, xh, DMODEL, FFDIM);
    }

    // logits = x @ Wf + bf
    hmma_gemm<false, false, true, false><<<gLogits, 256, GEMM_SMEM>>>(
        xh, wfh, wfl, bf, nullptr, out, nullptr, VOCAB, DMODEL);
}

// round 6
// speedup vs baseline: 12.1233x; 1.1407x over previous
#include <cuda_runtime.h>
#include <cuda_fp16.h>
#include <cstdint>

// Problem constants
#define VOCAB 32000
#define DMODEL 1024
#define NHEAD 16
#define HDIM 64
#define FFDIM 4096
#define NLAYER 4
#define SEQ 2048
#define BATCH 2
#define MTOK (BATCH * SEQ)      // 4096 token rows
#define HK (NHEAD * HDIM)       // 1024
#define QKVN 3072               // fused q|k|v output width

// ---------------------------------------------------------------------------
// Scratch (device globals; no allocations allowed)
// ---------------------------------------------------------------------------
__device__ float g_x[MTOK * DMODEL];                 // residual stream fp32
__device__ float g_qkv[MTOK * QKVN];                 // fused qkv fp32
__device__ float g_qkvb[NLAYER * QKVN];              // fused qkv bias
__device__ __half g_xh[MTOK * DMODEL];               // activations fp16
__device__ __half g_ah[MTOK * HK];
__device__ __half g_fh[MTOK * FFDIM];
// fp16 weights, NATURAL [K,N] layout, hi/lo
__device__ __half g_wqkvh[NLAYER * DMODEL * QKVN], g_wqkvl[NLAYER * DMODEL * QKVN];
__device__ __half g_woh[NLAYER * HK * DMODEL],     g_wol[NLAYER * HK * DMODEL];
__device__ __half g_w1h[NLAYER * DMODEL * FFDIM],  g_w1l[NLAYER * DMODEL * FFDIM];
__device__ __half g_w2h[NLAYER * FFDIM * DMODEL],  g_w2l[NLAYER * FFDIM * DMODEL];
__device__ __half g_wfh[DMODEL * VOCAB],           g_wfl[DMODEL * VOCAB];

// ---------------------------------------------------------------------------
// PTX helpers (all sm_80-era, arch-portable)
// ---------------------------------------------------------------------------
__device__ __forceinline__ uint32_t smem_u32(const void* p) {
    return (uint32_t)__cvta_generic_to_shared(p);
}
__device__ __forceinline__ void cp_async16(uint32_t dst, const void* src) {
    asm volatile("cp.async.cg.shared.global [%0], [%1], 16;\n" :: "r"(dst), "l"(src));
}
__device__ __forceinline__ void cp_commit() { asm volatile("cp.async.commit_group;\n" ::: "memory"); }
template<int N> __device__ __forceinline__ void cp_wait() {
    asm volatile("cp.async.wait_group %0;\n" :: "n"(N) : "memory");
}
__device__ __forceinline__ void ldsm_x4(uint32_t* r, uint32_t addr) {
    asm volatile("ldmatrix.sync.aligned.m8n8.x4.shared.b16 {%0,%1,%2,%3}, [%4];"
                 : "=r"(r[0]), "=r"(r[1]), "=r"(r[2]), "=r"(r[3]) : "r"(addr));
}
__device__ __forceinline__ void ldsm_x4_trans(uint32_t* r, uint32_t addr) {
    asm volatile("ldmatrix.sync.aligned.m8n8.x4.trans.shared.b16 {%0,%1,%2,%3}, [%4];"
                 : "=r"(r[0]), "=r"(r[1]), "=r"(r[2]), "=r"(r[3]) : "r"(addr));
}
__device__ __forceinline__ void mma_f16(float* c, const uint32_t* a, const uint32_t* b) {
    asm volatile(
        "mma.sync.aligned.m16n8k16.row.col.f32.f16.f16.f32 "
        "{%0,%1,%2,%3}, {%4,%5,%6,%7}, {%8,%9}, {%0,%1,%2,%3};"
        : "+f"(c[0]), "+f"(c[1]), "+f"(c[2]), "+f"(c[3])
        : "r"(a[0]), "r"(a[1]), "r"(a[2]), "r"(a[3]), "r"(b[0]), "r"(b[1]));
}

// ---------------------------------------------------------------------------
// fp16 hi/lo split helper
// ---------------------------------------------------------------------------
__device__ __forceinline__ void split_half(float v, __half& h, __half& l) {
    h = __float2half_rn(v);
    l = __float2half_rn(v - __half2float(h));
}

// ---------------------------------------------------------------------------
// Weight split (NO transpose): W [K,N] fp32 -> Wh/Wl [K,N] fp16 hi/lo.
// Optional column packing: out row stride ostride, column offset coff
// (used to pack Wq|Wk|Wv into the fused [D,3072] layout).
// One float4 per thread iteration; uint2 (4x fp16) stores. Pure bandwidth.
// ---------------------------------------------------------------------------
__global__ void wsplit_kernel(const float* __restrict__ W,
                              __half* __restrict__ Wh, __half* __restrict__ Wl,
                              long n4, int ncols4, int ostride4, int coff4)
{
    long stride = (long)gridDim.x * blockDim.x;
    for (long i = (long)blockIdx.x * blockDim.x + threadIdx.x; i < n4; i += stride) {
        float4 v = *(const float4*)(W + i * 4);
        __half2 h01, h23, l01, l23;
        split_half(v.x, h01.x, l01.x); split_half(v.y, h01.y, l01.y);
        split_half(v.z, h23.x, l23.x); split_half(v.w, h23.y, l23.y);
        long row = i / ncols4;
        long cg  = i - row * ncols4;
        long o = (row * ostride4 + coff4 + cg) * 4;
        __half2* ph = (__half2*)(Wh + o);
        __half2* pl = (__half2*)(Wl + o);
        ph[0] = h01; ph[1] = h23;
        pl[0] = l01; pl[1] = l23;
    }
}

// ---------------------------------------------------------------------------
// Embedding: x = emb[token] + pos ; also writes fp16
// ---------------------------------------------------------------------------
__global__ void embed_kernel(const int* __restrict__ tokens,
                             const float* __restrict__ emb,
                             const float* __restrict__ pos,
                             float* __restrict__ x,
                             __half* __restrict__ xh)
{
    int row = blockIdx.x;
    int s = row & (SEQ - 1);
    int t = tokens[row];
    const float4* e = (const float4*)(emb + (long)t * DMODEL);
    const float4* p = (const float4*)(pos + (long)s * DMODEL);
    for (int d = threadIdx.x; d < DMODEL / 4; d += blockDim.x) {
        float4 a = e[d], b = p[d];
        a.x += b.x; a.y += b.y; a.z += b.z; a.w += b.w;
        long o = (long)row * DMODEL + d * 4;
        *(float4*)&x[o] = a;
        __half2 h01, h23;
        h01.x = __float2half_rn(a.x); h01.y = __float2half_rn(a.y);
        h23.x = __float2half_rn(a.z); h23.y = __float2half_rn(a.w);
        *(__half2*)&xh[o] = h01; *(__half2*)&xh[o + 2] = h23;
    }
}

// qkv bias concat
__global__ void bias_concat_kernel(const float* __restrict__ bq, const float* __restrict__ bk,
                                   const float* __restrict__ bv, float* __restrict__ out)
{
    int i = blockIdx.x * blockDim.x + threadIdx.x;
    if (i >= NLAYER * QKVN) return;
    int l = i / QKVN, c = i - l * QKVN;
    float v = (c < 1024) ? bq[l * 1024 + c]
            : (c < 2048) ? bk[l * 1024 + c - 1024]
                         : bv[l * 1024 + c - 2048];
    out[i] = v;
}

// ---------------------------------------------------------------------------
// HMMA GEMM: C[M,N] = A[M,K] @ B  (A fp16 [M,K]; B fp16 [K,N] hi/lo, natural)
// 2-pass split: D = A*Bh + A*Bl, fp32 accum in registers.
// CTA 128x128, BK=32, 8 warps (2x4), warp tile 64x32, mma.sync m16n8k16.
// B fragments via ldmatrix.x4.trans from [K,N] tiles.
// 3-stage cp.async pipeline, one __syncthreads per k-chunk.
// ---------------------------------------------------------------------------
#define ASTRIDE 80                  // A smem row stride bytes (32 halves + pad)
#define ATILE_B 10240               // [128][40] halves
#define BSTRIDE 272                 // B smem row stride bytes (128 halves + pad)
#define BTILE_B 8704                // [32][136] halves
#define STAGE_B (ATILE_B + 2 * BTILE_B)   // 27648
#define GEMM_SMEM (3 * STAGE_B)           // 82944

template<bool RELU, bool RESID, bool WF32, bool WH16>
__global__ __launch_bounds__(256)
void hmma_gemm(const __half* __restrict__ A,
               const __half* __restrict__ Bh, const __half* __restrict__ Bl,
               const float* __restrict__ bias, const float* __restrict__ resid,
               float* __restrict__ Cf, __half* __restrict__ Ch,
               int N, int K)
{
    extern __shared__ char smem[];
    uint32_t sbase = smem_u32(smem);

    int tid = threadIdx.x;
    int lane = tid & 31;
    int wid = tid >> 5;
    int wm = wid & 1;          // 2 warps over M (64 rows each)
    int wn = wid >> 1;         // 4 warps over N (32 cols each)
    int row0 = blockIdx.x * 128;
    int ncol0 = blockIdx.y * 128;
    int nk = K >> 5;

    float c[4][4][4];
#pragma unroll
    for (int i = 0; i < 4; i++)
#pragma unroll
        for (int j = 0; j < 4; j++)
#pragma unroll
            for (int k = 0; k < 4; k++) c[i][j][k] = 0.f;

    auto load_stage = [&](int chunk, int buf) {
        uint32_t sb = sbase + buf * STAGE_B;
        int kc = chunk << 5;
        // A: 128 rows x 64B  (512 cp)
#pragma unroll 2
        for (int i = tid; i < 512; i += 256) {
            int r = i >> 2, cc = i & 3;
            cp_async16(sb + (uint32_t)(r * ASTRIDE + cc * 16),
                       A + (long)(row0 + r) * K + kc + cc * 8);
        }
        // B: 32 k-rows x 256B for hi and lo (512 cp each)
#pragma unroll 4
        for (int i = tid; i < 512; i += 256) {
            int r = i >> 4, cc = i & 15;
            uint32_t d = sb + ATILE_B + (uint32_t)(r * BSTRIDE + cc * 16);
            long g = (long)(kc + r) * N + ncol0 + cc * 8;
            cp_async16(d,           Bh + g);
            cp_async16(d + BTILE_B, Bl + g);
        }
        cp_commit();
    };

    load_stage(0, 0);
    load_stage(1, 1);

    // A ldmatrix addressing (row-major, non-trans)
    int arow = (lane & 7) + ((lane >> 3) & 1) * 8;
    int akk = ((lane >> 4) & 1) * 8;
    // B ldmatrix addressing (trans): group t = lane/8
    int bt = lane >> 3, br = lane & 7;
    int brow_off = (bt & 1) * 8 + br;       // k within 16
    int bcol_off = (bt >> 1) * 8;           // n within 16

    for (int ch = 0; ch < nk; ch++) {
        int buf = ch % 3;
        if (ch + 1 < nk) cp_wait<1>(); else cp_wait<0>();
        __syncthreads();
        if (ch + 2 < nk) load_stage(ch + 2, (ch + 2) % 3);

        uint32_t sb = sbase + buf * STAGE_B;
#pragma unroll
        for (int ks = 0; ks < 2; ks++) {
            int k0 = ks * 16;
            uint32_t a_r[4][4], b_h[4][2], b_l[4][2];
#pragma unroll
            for (int mi = 0; mi < 4; mi++) {
                uint32_t ad = sb + (uint32_t)((wm * 64 + mi * 16 + arow) * ASTRIDE
                                              + (k0 + akk) * 2);
                ldsm_x4(a_r[mi], ad);
            }
#pragma unroll
            for (int p = 0; p < 2; p++) {
                uint32_t bd = sb + ATILE_B
                            + (uint32_t)((k0 + brow_off) * BSTRIDE
                                         + (wn * 32 + p * 16 + bcol_off) * 2);
                uint32_t r[4];
                ldsm_x4_trans(r, bd);
                b_h[2 * p][0] = r[0]; b_h[2 * p][1] = r[1];
                b_h[2 * p + 1][0] = r[2]; b_h[2 * p + 1][1] = r[3];
                ldsm_x4_trans(r, bd + BTILE_B);
                b_l[2 * p][0] = r[0]; b_l[2 * p][1] = r[1];
                b_l[2 * p + 1][0] = r[2]; b_l[2 * p + 1][1] = r[3];
            }
#pragma unroll
            for (int mi = 0; mi < 4; mi++)
#pragma unroll
                for (int ni = 0; ni < 4; ni++) {
                    mma_f16(c[mi][ni], a_r[mi], b_h[ni]);
                    mma_f16(c[mi][ni], a_r[mi], b_l[ni]);
                }
        }
    }

    // Epilogue
    int rbase = row0 + wm * 64 + (lane >> 2);
    int cbase = ncol0 + wn * 32 + (lane & 3) * 2;
#pragma unroll
    for (int mi = 0; mi < 4; mi++) {
#pragma unroll
        for (int ni = 0; ni < 4; ni++) {
            int gc = cbase + ni * 8;
            float b0 = __ldg(&bias[gc]), b1 = __ldg(&bias[gc + 1]);
#pragma unroll
            for (int half_ = 0; half_ < 2; half_++) {
                long gr = rbase + mi * 16 + half_ * 8;
                float v0 = c[mi][ni][half_ * 2 + 0] + b0;
                float v1 = c[mi][ni][half_ * 2 + 1] + b1;
                if (RELU) { v0 = fmaxf(v0, 0.f); v1 = fmaxf(v1, 0.f); }
                if (RESID) {
                    float2 rr = *(const float2*)&resid[gr * N + gc];
                    v0 += rr.x; v1 += rr.y;
                }
                if (WF32) {
                    float2 o; o.x = v0; o.y = v1;
                    *(float2*)&Cf[gr * N + gc] = o;
                }
                if (WH16) {
                    __half2 hh;
                    hh.x = __float2half_rn(v0); hh.y = __float2half_rn(v1);
                    *(__half2*)&Ch[gr * N + gc] = hh;
                }
            }
        }
    }
}

// ---------------------------------------------------------------------------
// Flash attention (fp32), reads fused qkv [M,3072], writes fp16 attn out
// ---------------------------------------------------------------------------
#define FPAD 68

__global__ __launch_bounds__(256)
void flash_attn_kernel(const float* __restrict__ QKV,
                       __half* __restrict__ Ao)
{
    extern __shared__ float sm[];
    float* Qs = sm;
    float* Ks = sm + 64 * FPAD;
    float* Vs = sm + 2 * 64 * FPAD;
    float* Ps = sm + 3 * 64 * FPAD;

    int qt = gridDim.x - 1 - blockIdx.x;
    int bh = blockIdx.y;
    int b = bh >> 4;
    int h = bh & 15;
    int tid = threadIdx.x;
    int tx = tid & 15;
    int ty = tid >> 4;

    long baseq = (long)b * SEQ * QKVN + h * HDIM;
    long basek = baseq + 1024;
    long basev = baseq + 2048;

    for (int i = tid; i < 64 * 16; i += 256) {
        int r = i >> 4, c4 = (i & 15) * 4;
        *(float4*)&Qs[r * FPAD + c4] =
            *(const float4*)&QKV[baseq + (long)(qt * 64 + r) * QKVN + c4];
    }

    float m[4], l[4], o[4][4];
#pragma unroll
    for (int i = 0; i < 4; i++) {
        m[i] = -1e30f; l[i] = 0.f;
#pragma unroll
        for (int j = 0; j < 4; j++) o[i][j] = 0.f;
    }

    for (int jt = 0; jt <= qt; jt++) {
        for (int i = tid; i < 64 * 16; i += 256) {
            int r = i >> 4, c4 = (i & 15) * 4;
            long off = (long)(jt * 64 + r) * QKVN + c4;
            *(float4*)&Ks[r * FPAD + c4] = *(const float4*)&QKV[basek + off];
            *(float4*)&Vs[r * FPAD + c4] = *(const float4*)&QKV[basev + off];
        }
        __syncthreads();

        float s[4][4];
#pragma unroll
        for (int i = 0; i < 4; i++)
#pragma unroll
            for (int j = 0; j < 4; j++) s[i][j] = 0.f;

#pragma unroll 4
        for (int k4 = 0; k4 < HDIM; k4 += 4) {
            float4 qv[4], kv[4];
#pragma unroll
            for (int i = 0; i < 4; i++)
                qv[i] = *(const float4*)&Qs[(ty * 4 + i) * FPAD + k4];
#pragma unroll
            for (int j = 0; j < 4; j++)
                kv[j] = *(const float4*)&Ks[(tx + 16 * j) * FPAD + k4];
#pragma unroll
            for (int i = 0; i < 4; i++)
#pragma unroll
                for (int j = 0; j < 4; j++) {
                    s[i][j] = fmaf(qv[i].x, kv[j].x, s[i][j]);
                    s[i][j] = fmaf(qv[i].y, kv[j].y, s[i][j]);
                    s[i][j] = fmaf(qv[i].z, kv[j].z, s[i][j]);
                    s[i][j] = fmaf(qv[i].w, kv[j].w, s[i][j]);
                }
        }

        if (jt == qt) {
#pragma unroll
            for (int i = 0; i < 4; i++) {
                int qloc = ty * 4 + i;
#pragma unroll
                for (int j = 0; j < 4; j++) {
                    int kloc = tx + 16 * j;
                    s[i][j] = (kloc > qloc) ? -1e30f : s[i][j] * 0.125f;
                }
            }
        } else {
#pragma unroll
            for (int i = 0; i < 4; i++)
#pragma unroll
                for (int j = 0; j < 4; j++) s[i][j] *= 0.125f;
        }

#pragma unroll
        for (int i = 0; i < 4; i++) {
            float rmax = fmaxf(fmaxf(s[i][0], s[i][1]), fmaxf(s[i][2], s[i][3]));
#pragma unroll
            for (int w = 1; w < 16; w <<= 1)
                rmax = fmaxf(rmax, __shfl_xor_sync(0xffffffffu, rmax, w));
            float mn = fmaxf(m[i], rmax);
            float corr = __expf(m[i] - mn);
            float rsum = 0.f;
#pragma unroll
            for (int j = 0; j < 4; j++) {
                float p = __expf(s[i][j] - mn);
                s[i][j] = p;
                rsum += p;
            }
#pragma unroll
            for (int w = 1; w < 16; w <<= 1)
                rsum += __shfl_xor_sync(0xffffffffu, rsum, w);
            l[i] = l[i] * corr + rsum;
            m[i] = mn;
#pragma unroll
            for (int j = 0; j < 4; j++) o[i][j] *= corr;
        }

#pragma unroll
        for (int i = 0; i < 4; i++)
#pragma unroll
            for (int j = 0; j < 4; j++)
                Ps[(ty * 4 + i) * FPAD + tx + 16 * j] = s[i][j];
        __syncthreads();

#pragma unroll 4
        for (int k4 = 0; k4 < 64; k4 += 4) {
            float4 pv[4];
#pragma unroll
            for (int i = 0; i < 4; i++)
                pv[i] = *(const float4*)&Ps[(ty * 4 + i) * FPAD + k4];
#pragma unroll
            for (int cc = 0; cc < 4; cc++) {
                float4 vv = *(const float4*)&Vs[(k4 + cc) * FPAD + tx * 4];
#pragma unroll
                for (int i = 0; i < 4; i++) {
                    float p = (cc == 0) ? pv[i].x : (cc == 1) ? pv[i].y
                              : (cc == 2) ? pv[i].z : pv[i].w;
                    o[i][0] = fmaf(p, vv.x, o[i][0]);
                    o[i][1] = fmaf(p, vv.y, o[i][1]);
                    o[i][2] = fmaf(p, vv.z, o[i][2]);
                    o[i][3] = fmaf(p, vv.w, o[i][3]);
                }
            }
        }
        __syncthreads();
    }

#pragma unroll
    for (int i = 0; i < 4; i++) {
        float inv = 1.0f / l[i];
        int qg = qt * 64 + ty * 4 + i;
        __half2 h01, h23;
        h01.x = __float2half_rn(o[i][0] * inv);
        h01.y = __float2half_rn(o[i][1] * inv);
        h23.x = __float2half_rn(o[i][2] * inv);
        h23.y = __float2half_rn(o[i][3] * inv);
        long oaddr = (long)(b * SEQ + qg) * HK + h * HDIM + tx * 4;
        *(__half2*)&Ao[oaddr] = h01; *(__half2*)&Ao[oaddr + 2] = h23;
    }
}

#define FLASH_SMEM (4 * 64 * FPAD * 4)

// ---------------------------------------------------------------------------
// Launch
// ---------------------------------------------------------------------------
extern "C" void kernel_launch(void* const* d_in, const int* in_sizes, int n_in,
                              void* d_out, int out_size)
{
    const int*   tokens = (const int*)  d_in[0];
    const float* emb    = (const float*)d_in[1];
    const float* pos    = (const float*)d_in[2];
    const float* Wq     = (const float*)d_in[3];
    const float* bq     = (const float*)d_in[4];
    const float* Wk     = (const float*)d_in[5];
    const float* bk     = (const float*)d_in[6];
    const float* Wv     = (const float*)d_in[7];
    const float* bv     = (const float*)d_in[8];
    const float* Wo     = (const float*)d_in[9];
    const float* bo     = (const float*)d_in[10];
    const float* W1     = (const float*)d_in[11];
    const float* b1     = (const float*)d_in[12];
    const float* W2     = (const float*)d_in[13];
    const float* b2     = (const float*)d_in[14];
    const float* Wf     = (const float*)d_in[15];
    const float* bf     = (const float*)d_in[16];
    float* out = (float*)d_out;

    float *x, *qkv, *qkvb;
    __half *xh, *ah, *fh;
    __half *wqkvh, *wqkvl, *woh, *wol, *w1h, *w1l, *w2h, *w2l, *wfh, *wfl;
    cudaGetSymbolAddress((void**)&x, g_x);
    cudaGetSymbolAddress((void**)&qkv, g_qkv);
    cudaGetSymbolAddress((void**)&qkvb, g_qkvb);
    cudaGetSymbolAddress((void**)&xh, g_xh);
    cudaGetSymbolAddress((void**)&ah, g_ah);
    cudaGetSymbolAddress((void**)&fh, g_fh);
    cudaGetSymbolAddress((void**)&wqkvh, g_wqkvh); cudaGetSymbolAddress((void**)&wqkvl, g_wqkvl);
    cudaGetSymbolAddress((void**)&woh, g_woh); cudaGetSymbolAddress((void**)&wol, g_wol);
    cudaGetSymbolAddress((void**)&w1h, g_w1h); cudaGetSymbolAddress((void**)&w1l, g_w1l);
    cudaGetSymbolAddress((void**)&w2h, g_w2h); cudaGetSymbolAddress((void**)&w2l, g_w2l);
    cudaGetSymbolAddress((void**)&wfh, g_wfh); cudaGetSymbolAddress((void**)&wfl, g_wfl);

    static bool attr_set = false;
    if (!attr_set) {
        cudaFuncSetAttribute(flash_attn_kernel,
                             cudaFuncAttributeMaxDynamicSharedMemorySize, FLASH_SMEM);
        cudaFuncSetAttribute(hmma_gemm<false, false, true, false>,
                             cudaFuncAttributeMaxDynamicSharedMemorySize, GEMM_SMEM);
        cudaFuncSetAttribute(hmma_gemm<false, true, true, true>,
                             cudaFuncAttributeMaxDynamicSharedMemorySize, GEMM_SMEM);
        cudaFuncSetAttribute(hmma_gemm<true, false, false, true>,
                             cudaFuncAttributeMaxDynamicSharedMemorySize, GEMM_SMEM);
        attr_set = true;
    }

    // ---- weight split (no transpose; [K,N] natural layout) ----
    for (int l = 0; l < NLAYER; l++) {
        long DK = (long)DMODEL * HK;           // 1M elements, n4 = 262144
        // Wq|Wk|Wv packed into fused [D,3072] rows
        wsplit_kernel<<<1024, 256>>>(Wq + l * DK,
            wqkvh + (long)l * DMODEL * QKVN, wqkvl + (long)l * DMODEL * QKVN,
            DK / 4, HK / 4, QKVN / 4, 0);
        wsplit_kernel<<<1024, 256>>>(Wk + l * DK,
            wqkvh + (long)l * DMODEL * QKVN, wqkvl + (long)l * DMODEL * QKVN,
            DK / 4, HK / 4, QKVN / 4, 1024 / 4);
        wsplit_kernel<<<1024, 256>>>(Wv + l * DK,
            wqkvh + (long)l * DMODEL * QKVN, wqkvl + (long)l * DMODEL * QKVN,
            DK / 4, HK / 4, QKVN / 4, 2048 / 4);
        wsplit_kernel<<<1024, 256>>>(Wo + l * DK,
            woh + (long)l * HK * DMODEL, wol + (long)l * HK * DMODEL,
            DK / 4, DMODEL / 4, DMODEL / 4, 0);
        long DF = (long)DMODEL * FFDIM;        // 4M
        wsplit_kernel<<<2048, 256>>>(W1 + l * DF,
            w1h + (long)l * DF, w1l + (long)l * DF,
            DF / 4, FFDIM / 4, FFDIM / 4, 0);
        wsplit_kernel<<<2048, 256>>>(W2 + l * DF,
            w2h + (long)l * DF, w2l + (long)l * DF,
            DF / 4, DMODEL / 4, DMODEL / 4, 0);
    }
    wsplit_kernel<<<8192, 256>>>(Wf, wfh, wfl,
        (long)DMODEL * VOCAB / 4, VOCAB / 4, VOCAB / 4, 0);
    bias_concat_kernel<<<(NLAYER * QKVN + 255) / 256, 256>>>(bq, bk, bv, qkvb);

    // ---- forward ----
    embed_kernel<<<MTOK, 256>>>(tokens, emb, pos, x, xh);

    dim3 gQKV(MTOK / 128, QKVN / 128);
    dim3 gProj(MTOK / 128, DMODEL / 128);
    dim3 gFF1(MTOK / 128, FFDIM / 128);
    dim3 gLogits(MTOK / 128, VOCAB / 128);
    dim3 gAttn(SEQ / 64, BATCH * NHEAD);

    for (int l = 0; l < NLAYER; l++) {
        const __half* wqh = wqkvh + (long)l * DMODEL * QKVN;
        const __half* wql = wqkvl + (long)l * DMODEL * QKVN;

        // qkv = x @ Wqkv + b  (fp32 out)
        hmma_gemm<false, false, true, false><<<gQKV, 256, GEMM_SMEM>>>(
            xh, wqh, wql, qkvb + (long)l * QKVN, nullptr,
            qkv, nullptr, QKVN, DMODEL);

        flash_attn_kernel<<<gAttn, 256, FLASH_SMEM>>>(qkv, ah);

        // x = x + a @ Wo + bo  (fp32 + fp16 out)
        hmma_gemm<false, true, true, true><<<gProj, 256, GEMM_SMEM>>>(
            ah, woh + (long)l * HK * DMODEL, wol + (long)l * HK * DMODEL,
            bo + (long)l * DMODEL, x, x, xh, DMODEL, HK);

        // f = relu(x @ W1 + b1)  (fp16 only)
        hmma_gemm<true, false, false, true><<<gFF1, 256, GEMM_SMEM>>>(
            xh, w1h + (long)l * DMODEL * FFDIM, w1l + (long)l * DMODEL * FFDIM,
            b1 + (long)l * FFDIM, nullptr, nullptr, fh, FFDIM, DMODEL);

        // x = x + f @ W2 + b2
        hmma_gemm<false, true, true, true><<<gProj, 256, GEMM_SMEM>>>(
            fh, w2h + (long)l * FFDIM * DMODEL, w2l + (long)l * FFDIM * DMODEL,
            b2 + (long)l * DMODEL, x, x, xh, DMODEL, FFDIM);
    }

    // logits = x @ Wf + bf
    hmma_gemm<false, false, true, false><<<gLogits, 256, GEMM_SMEM>>>(
        xh, wfh, wfl, bf, nullptr, out, nullptr, VOCAB, DMODEL);
}

// round 7
// speedup vs baseline: 15.5370x; 1.2816x over previous
#include <cuda_runtime.h>
#include <cuda_fp16.h>
#include <cstdint>

// Problem constants
#define VOCAB 32000
#define DMODEL 1024
#define NHEAD 16
#define HDIM 64
#define FFDIM 4096
#define NLAYER 4
#define SEQ 2048
#define BATCH 2
#define MTOK (BATCH * SEQ)      // 4096 token rows
#define HK (NHEAD * HDIM)       // 1024
#define QKVN 3072               // fused q|k|v output width

// ---------------------------------------------------------------------------
// Scratch (device globals; no allocations allowed)
// ---------------------------------------------------------------------------
__device__ float g_x[MTOK * DMODEL];                 // residual stream fp32
__device__ float g_qkv[MTOK * QKVN];                 // fused qkv fp32
__device__ float g_qkvb[NLAYER * QKVN];              // fused qkv bias
__device__ __half g_xh[MTOK * DMODEL];               // activations fp16
__device__ __half g_ah[MTOK * HK];
__device__ __half g_fh[MTOK * FFDIM];
// fp16 weights, NATURAL [K,N] layout
__device__ __half g_wqkv[NLAYER * DMODEL * QKVN];
__device__ __half g_wo[NLAYER * HK * DMODEL];
__device__ __half g_w1[NLAYER * DMODEL * FFDIM];
__device__ __half g_w2[NLAYER * FFDIM * DMODEL];
__device__ __half g_wf[DMODEL * VOCAB];

// ---------------------------------------------------------------------------
// PTX helpers (all sm_80-era, arch-portable)
// ---------------------------------------------------------------------------
__device__ __forceinline__ uint32_t smem_u32(const void* p) {
    return (uint32_t)__cvta_generic_to_shared(p);
}
__device__ __forceinline__ void cp_async16(uint32_t dst, const void* src) {
    asm volatile("cp.async.cg.shared.global [%0], [%1], 16;\n" :: "r"(dst), "l"(src));
}
__device__ __forceinline__ void cp_commit() { asm volatile("cp.async.commit_group;\n" ::: "memory"); }
template<int N> __device__ __forceinline__ void cp_wait() {
    asm volatile("cp.async.wait_group %0;\n" :: "n"(N) : "memory");
}
__device__ __forceinline__ void ldsm_x4(uint32_t* r, uint32_t addr) {
    asm volatile("ldmatrix.sync.aligned.m8n8.x4.shared.b16 {%0,%1,%2,%3}, [%4];"
                 : "=r"(r[0]), "=r"(r[1]), "=r"(r[2]), "=r"(r[3]) : "r"(addr));
}
__device__ __forceinline__ void ldsm_x4_trans(uint32_t* r, uint32_t addr) {
    asm volatile("ldmatrix.sync.aligned.m8n8.x4.trans.shared.b16 {%0,%1,%2,%3}, [%4];"
                 : "=r"(r[0]), "=r"(r[1]), "=r"(r[2]), "=r"(r[3]) : "r"(addr));
}
__device__ __forceinline__ void mma_f16(float* c, const uint32_t* a, const uint32_t* b) {
    asm volatile(
        "mma.sync.aligned.m16n8k16.row.col.f32.f16.f16.f32 "
        "{%0,%1,%2,%3}, {%4,%5,%6,%7}, {%8,%9}, {%0,%1,%2,%3};"
        : "+f"(c[0]), "+f"(c[1]), "+f"(c[2]), "+f"(c[3])
        : "r"(a[0]), "r"(a[1]), "r"(a[2]), "r"(a[3]), "r"(b[0]), "r"(b[1]));
}

// ---------------------------------------------------------------------------
// Weight convert (NO transpose): W [K,N] fp32 -> fp16 [K,N], optional col pack.
// ---------------------------------------------------------------------------
__global__ void wsplit_kernel(const float* __restrict__ W,
                              __half* __restrict__ Wh,
                              long n4, int ncols4, int ostride4, int coff4)
{
    long stride = (long)gridDim.x * blockDim.x;
    for (long i = (long)blockIdx.x * blockDim.x + threadIdx.x; i < n4; i += stride) {
        float4 v = *(const float4*)(W + i * 4);
        __half2 h01, h23;
        h01.x = __float2half_rn(v.x); h01.y = __float2half_rn(v.y);
        h23.x = __float2half_rn(v.z); h23.y = __float2half_rn(v.w);
        long row = i / ncols4;
        long cg  = i - row * ncols4;
        long o = (row * ostride4 + coff4 + cg) * 4;
        __half2* ph = (__half2*)(Wh + o);
        ph[0] = h01; ph[1] = h23;
    }
}

// ---------------------------------------------------------------------------
// Embedding: x = emb[token] + pos ; also writes fp16
// ---------------------------------------------------------------------------
__global__ void embed_kernel(const int* __restrict__ tokens,
                             const float* __restrict__ emb,
                             const float* __restrict__ pos,
                             float* __restrict__ x,
                             __half* __restrict__ xh)
{
    int row = blockIdx.x;
    int s = row & (SEQ - 1);
    int t = tokens[row];
    const float4* e = (const float4*)(emb + (long)t * DMODEL);
    const float4* p = (const float4*)(pos + (long)s * DMODEL);
    for (int d = threadIdx.x; d < DMODEL / 4; d += blockDim.x) {
        float4 a = e[d], b = p[d];
        a.x += b.x; a.y += b.y; a.z += b.z; a.w += b.w;
        long o = (long)row * DMODEL + d * 4;
        *(float4*)&x[o] = a;
        __half2 h01, h23;
        h01.x = __float2half_rn(a.x); h01.y = __float2half_rn(a.y);
        h23.x = __float2half_rn(a.z); h23.y = __float2half_rn(a.w);
        *(__half2*)&xh[o] = h01; *(__half2*)&xh[o + 2] = h23;
    }
}

// qkv bias concat
__global__ void bias_concat_kernel(const float* __restrict__ bq, const float* __restrict__ bk,
                                   const float* __restrict__ bv, float* __restrict__ out)
{
    int i = blockIdx.x * blockDim.x + threadIdx.x;
    if (i >= NLAYER * QKVN) return;
    int l = i / QKVN, c = i - l * QKVN;
    float v = (c < 1024) ? bq[l * 1024 + c]
            : (c < 2048) ? bk[l * 1024 + c - 1024]
                         : bv[l * 1024 + c - 2048];
    out[i] = v;
}

// ---------------------------------------------------------------------------
// HMMA GEMM: C[M,N] = A[M,K] @ B  (A fp16 [M,K]; B fp16 [K,N] natural)
// Single pass, fp32 accum in registers.
// CTA 128x128, BK=32, 8 warps (2x4), warp tile 64x32, mma.sync m16n8k16.
// B fragments via ldmatrix.x4.trans from [K,N] tiles.
// 4-stage cp.async pipeline, one __syncthreads per k-chunk.
// ---------------------------------------------------------------------------
#define ASTRIDE 80                  // A smem row stride bytes (32 halves + pad)
#define ATILE_B 10240               // [128][40] halves
#define BSTRIDE 272                 // B smem row stride bytes (128 halves + pad)
#define BTILE_B 8704                // [32][136] halves
#define STAGE_B (ATILE_B + BTILE_B)       // 18944
#define GEMM_SMEM (4 * STAGE_B)           // 75776

template<bool RELU, bool RESID, bool WF32, bool WH16>
__global__ __launch_bounds__(256)
void hmma_gemm(const __half* __restrict__ A, const __half* __restrict__ B,
               const float* __restrict__ bias, const float* __restrict__ resid,
               float* __restrict__ Cf, __half* __restrict__ Ch,
               int N, int K)
{
    extern __shared__ char smem[];
    uint32_t sbase = smem_u32(smem);

    int tid = threadIdx.x;
    int lane = tid & 31;
    int wid = tid >> 5;
    int wm = wid & 1;          // 2 warps over M (64 rows each)
    int wn = wid >> 1;         // 4 warps over N (32 cols each)
    int row0 = blockIdx.x * 128;
    int ncol0 = blockIdx.y * 128;
    int nk = K >> 5;           // >= 32 here

    float c[4][4][4];
#pragma unroll
    for (int i = 0; i < 4; i++)
#pragma unroll
        for (int j = 0; j < 4; j++)
#pragma unroll
            for (int k = 0; k < 4; k++) c[i][j][k] = 0.f;

    auto load_stage = [&](int chunk, int buf) {
        uint32_t sb = sbase + buf * STAGE_B;
        int kc = chunk << 5;
        // A: 128 rows x 64B  (512 cp)
#pragma unroll 2
        for (int i = tid; i < 512; i += 256) {
            int r = i >> 2, cc = i & 3;
            cp_async16(sb + (uint32_t)(r * ASTRIDE + cc * 16),
                       A + (long)(row0 + r) * K + kc + cc * 8);
        }
        // B: 32 k-rows x 256B (512 cp)
#pragma unroll 2
        for (int i = tid; i < 512; i += 256) {
            int r = i >> 4, cc = i & 15;
            cp_async16(sb + ATILE_B + (uint32_t)(r * BSTRIDE + cc * 16),
                       B + (long)(kc + r) * N + ncol0 + cc * 8);
        }
        cp_commit();
    };

    load_stage(0, 0);
    load_stage(1, 1);
    load_stage(2, 2);

    // A ldmatrix addressing (row-major, non-trans)
    int arow = (lane & 7) + ((lane >> 3) & 1) * 8;
    int akk = ((lane >> 4) & 1) * 8;
    // B ldmatrix addressing (trans): group t = lane/8
    int bt = lane >> 3, br = lane & 7;
    int brow_off = (bt & 1) * 8 + br;       // k within 16
    int bcol_off = (bt >> 1) * 8;           // n within 16

    for (int ch = 0; ch < nk; ch++) {
        int buf = ch & 3;
        if (ch + 2 < nk)      cp_wait<2>();
        else if (ch + 1 < nk) cp_wait<1>();
        else                  cp_wait<0>();
        __syncthreads();
        if (ch + 3 < nk) load_stage(ch + 3, (ch + 3) & 3);

        uint32_t sb = sbase + buf * STAGE_B;
#pragma unroll
        for (int ks = 0; ks < 2; ks++) {
            int k0 = ks * 16;
            uint32_t a_r[4][4], b_r[4][2];
#pragma unroll
            for (int mi = 0; mi < 4; mi++) {
                uint32_t ad = sb + (uint32_t)((wm * 64 + mi * 16 + arow) * ASTRIDE
                                              + (k0 + akk) * 2);
                ldsm_x4(a_r[mi], ad);
            }
#pragma unroll
            for (int p = 0; p < 2; p++) {
                uint32_t bd = sb + ATILE_B
                            + (uint32_t)((k0 + brow_off) * BSTRIDE
                                         + (wn * 32 + p * 16 + bcol_off) * 2);
                uint32_t r[4];
                ldsm_x4_trans(r, bd);
                b_r[2 * p][0] = r[0]; b_r[2 * p][1] = r[1];
                b_r[2 * p + 1][0] = r[2]; b_r[2 * p + 1][1] = r[3];
            }
#pragma unroll
            for (int mi = 0; mi < 4; mi++)
#pragma unroll
                for (int ni = 0; ni < 4; ni++)
                    mma_f16(c[mi][ni], a_r[mi], b_r[ni]);
        }
    }

    // Epilogue
    int rbase = row0 + wm * 64 + (lane >> 2);
    int cbase = ncol0 + wn * 32 + (lane & 3) * 2;
#pragma unroll
    for (int mi = 0; mi < 4; mi++) {
#pragma unroll
        for (int ni = 0; ni < 4; ni++) {
            int gc = cbase + ni * 8;
            float b0 = __ldg(&bias[gc]), b1 = __ldg(&bias[gc + 1]);
#pragma unroll
            for (int half_ = 0; half_ < 2; half_++) {
                long gr = rbase + mi * 16 + half_ * 8;
                float v0 = c[mi][ni][half_ * 2 + 0] + b0;
                float v1 = c[mi][ni][half_ * 2 + 1] + b1;
                if (RELU) { v0 = fmaxf(v0, 0.f); v1 = fmaxf(v1, 0.f); }
                if (RESID) {
                    float2 rr = *(const float2*)&resid[gr * N + gc];
                    v0 += rr.x; v1 += rr.y;
                }
                if (WF32) {
                    float2 o; o.x = v0; o.y = v1;
                    *(float2*)&Cf[gr * N + gc] = o;
                }
                if (WH16) {
                    __half2 hh;
                    hh.x = __float2half_rn(v0); hh.y = __float2half_rn(v1);
                    *(__half2*)&Ch[gr * N + gc] = hh;
                }
            }
        }
    }
}

// ---------------------------------------------------------------------------
// Flash attention (fp32), reads fused qkv [M,3072], writes fp16 attn out
// ---------------------------------------------------------------------------
#define FPAD 68

__global__ __launch_bounds__(256)
void flash_attn_kernel(const float* __restrict__ QKV,
                       __half* __restrict__ Ao)
{
    extern __shared__ float sm[];
    float* Qs = sm;
    float* Ks = sm + 64 * FPAD;
    float* Vs = sm + 2 * 64 * FPAD;
    float* Ps = sm + 3 * 64 * FPAD;

    int qt = gridDim.x - 1 - blockIdx.x;
    int bh = blockIdx.y;
    int b = bh >> 4;
    int h = bh & 15;
    int tid = threadIdx.x;
    int tx = tid & 15;
    int ty = tid >> 4;

    long baseq = (long)b * SEQ * QKVN + h * HDIM;
    long basek = baseq + 1024;
    long basev = baseq + 2048;

    for (int i = tid; i < 64 * 16; i += 256) {
        int r = i >> 4, c4 = (i & 15) * 4;
        *(float4*)&Qs[r * FPAD + c4] =
            *(const float4*)&QKV[baseq + (long)(qt * 64 + r) * QKVN + c4];
    }

    float m[4], l[4], o[4][4];
#pragma unroll
    for (int i = 0; i < 4; i++) {
        m[i] = -1e30f; l[i] = 0.f;
#pragma unroll
        for (int j = 0; j < 4; j++) o[i][j] = 0.f;
    }

    for (int jt = 0; jt <= qt; jt++) {
        for (int i = tid; i < 64 * 16; i += 256) {
            int r = i >> 4, c4 = (i & 15) * 4;
            long off = (long)(jt * 64 + r) * QKVN + c4;
            *(float4*)&Ks[r * FPAD + c4] = *(const float4*)&QKV[basek + off];
            *(float4*)&Vs[r * FPAD + c4] = *(const float4*)&QKV[basev + off];
        }
        __syncthreads();

        float s[4][4];
#pragma unroll
        for (int i = 0; i < 4; i++)
#pragma unroll
            for (int j = 0; j < 4; j++) s[i][j] = 0.f;

#pragma unroll 4
        for (int k4 = 0; k4 < HDIM; k4 += 4) {
            float4 qv[4], kv[4];
#pragma unroll
            for (int i = 0; i < 4; i++)
                qv[i] = *(const float4*)&Qs[(ty * 4 + i) * FPAD + k4];
#pragma unroll
            for (int j = 0; j < 4; j++)
                kv[j] = *(const float4*)&Ks[(tx + 16 * j) * FPAD + k4];
#pragma unroll
            for (int i = 0; i < 4; i++)
#pragma unroll
                for (int j = 0; j < 4; j++) {
                    s[i][j] = fmaf(qv[i].x, kv[j].x, s[i][j]);
                    s[i][j] = fmaf(qv[i].y, kv[j].y, s[i][j]);
                    s[i][j] = fmaf(qv[i].z, kv[j].z, s[i][j]);
                    s[i][j] = fmaf(qv[i].w, kv[j].w, s[i][j]);
                }
        }

        if (jt == qt) {
#pragma unroll
            for (int i = 0; i < 4; i++) {
                int qloc = ty * 4 + i;
#pragma unroll
                for (int j = 0; j < 4; j++) {
                    int kloc = tx + 16 * j;
                    s[i][j] = (kloc > qloc) ? -1e30f : s[i][j] * 0.125f;
                }
            }
        } else {
#pragma unroll
            for (int i = 0; i < 4; i++)
#pragma unroll
                for (int j = 0; j < 4; j++) s[i][j] *= 0.125f;
        }

#pragma unroll
        for (int i = 0; i < 4; i++) {
            float rmax = fmaxf(fmaxf(s[i][0], s[i][1]), fmaxf(s[i][2], s[i][3]));
#pragma unroll
            for (int w = 1; w < 16; w <<= 1)
                rmax = fmaxf(rmax, __shfl_xor_sync(0xffffffffu, rmax, w));
            float mn = fmaxf(m[i], rmax);
            float corr = __expf(m[i] - mn);
            float rsum = 0.f;
#pragma unroll
            for (int j = 0; j < 4; j++) {
                float p = __expf(s[i][j] - mn);
                s[i][j] = p;
                rsum += p;
            }
#pragma unroll
            for (int w = 1; w < 16; w <<= 1)
                rsum += __shfl_xor_sync(0xffffffffu, rsum, w);
            l[i] = l[i] * corr + rsum;
            m[i] = mn;
#pragma unroll
            for (int j = 0; j < 4; j++) o[i][j] *= corr;
        }

#pragma unroll
        for (int i = 0; i < 4; i++)
#pragma unroll
            for (int j = 0; j < 4; j++)
                Ps[(ty * 4 + i) * FPAD + tx + 16 * j] = s[i][j];
        __syncthreads();

#pragma unroll 4
        for (int k4 = 0; k4 < 64; k4 += 4) {
            float4 pv[4];
#pragma unroll
            for (int i = 0; i < 4; i++)
                pv[i] = *(const float4*)&Ps[(ty * 4 + i) * FPAD + k4];
#pragma unroll
            for (int cc = 0; cc < 4; cc++) {
                float4 vv = *(const float4*)&Vs[(k4 + cc) * FPAD + tx * 4];
#pragma unroll
                for (int i = 0; i < 4; i++) {
                    float p = (cc == 0) ? pv[i].x : (cc == 1) ? pv[i].y
                              : (cc == 2) ? pv[i].z : pv[i].w;
                    o[i][0] = fmaf(p, vv.x, o[i][0]);
                    o[i][1] = fmaf(p, vv.y, o[i][1]);
                    o[i][2] = fmaf(p, vv.z, o[i][2]);
                    o[i][3] = fmaf(p, vv.w, o[i][3]);
                }
            }
        }
        __syncthreads();
    }

#pragma unroll
    for (int i = 0; i < 4; i++) {
        float inv = 1.0f / l[i];
        int qg = qt * 64 + ty * 4 + i;
        __half2 h01, h23;
        h01.x = __float2half_rn(o[i][0] * inv);
        h01.y = __float2half_rn(o[i][1] * inv);
        h23.x = __float2half_rn(o[i][2] * inv);
        h23.y = __float2half_rn(o[i][3] * inv);
        long oaddr = (long)(b * SEQ + qg) * HK + h * HDIM + tx * 4;
        *(__half2*)&Ao[oaddr] = h01; *(__half2*)&Ao[oaddr + 2] = h23;
    }
}

#define FLASH_SMEM (4 * 64 * FPAD * 4)

// ---------------------------------------------------------------------------
// Launch
// ---------------------------------------------------------------------------
extern "C" void kernel_launch(void* const* d_in, const int* in_sizes, int n_in,
                              void* d_out, int out_size)
{
    const int*   tokens = (const int*)  d_in[0];
    const float* emb    = (const float*)d_in[1];
    const float* pos    = (const float*)d_in[2];
    const float* Wq     = (const float*)d_in[3];
    const float* bq     = (const float*)d_in[4];
    const float* Wk     = (const float*)d_in[5];
    const float* bk     = (const float*)d_in[6];
    const float* Wv     = (const float*)d_in[7];
    const float* bv     = (const float*)d_in[8];
    const float* Wo     = (const float*)d_in[9];
    const float* bo     = (const float*)d_in[10];
    const float* W1     = (const float*)d_in[11];
    const float* b1     = (const float*)d_in[12];
    const float* W2     = (const float*)d_in[13];
    const float* b2     = (const float*)d_in[14];
    const float* Wf     = (const float*)d_in[15];
    const float* bf     = (const float*)d_in[16];
    float* out = (float*)d_out;

    float *x, *qkv, *qkvb;
    __half *xh, *ah, *fh;
    __half *wqkv, *wo, *w1, *w2, *wf;
    cudaGetSymbolAddress((void**)&x, g_x);
    cudaGetSymbolAddress((void**)&qkv, g_qkv);
    cudaGetSymbolAddress((void**)&qkvb, g_qkvb);
    cudaGetSymbolAddress((void**)&xh, g_xh);
    cudaGetSymbolAddress((void**)&ah, g_ah);
    cudaGetSymbolAddress((void**)&fh, g_fh);
    cudaGetSymbolAddress((void**)&wqkv, g_wqkv);
    cudaGetSymbolAddress((void**)&wo, g_wo);
    cudaGetSymbolAddress((void**)&w1, g_w1);
    cudaGetSymbolAddress((void**)&w2, g_w2);
    cudaGetSymbolAddress((void**)&wf, g_wf);

    static bool attr_set = false;
    if (!attr_set) {
        cudaFuncSetAttribute(flash_attn_kernel,
                             cudaFuncAttributeMaxDynamicSharedMemorySize, FLASH_SMEM);
        cudaFuncSetAttribute(hmma_gemm<false, false, true, false>,
                             cudaFuncAttributeMaxDynamicSharedMemorySize, GEMM_SMEM);
        cudaFuncSetAttribute(hmma_gemm<false, true, true, true>,
                             cudaFuncAttributeMaxDynamicSharedMemorySize, GEMM_SMEM);
        cudaFuncSetAttribute(hmma_gemm<true, false, false, true>,
                             cudaFuncAttributeMaxDynamicSharedMemorySize, GEMM_SMEM);
        attr_set = true;
    }

    // ---- weight convert (no transpose; [K,N] natural layout) ----
    for (int l = 0; l < NLAYER; l++) {
        long DK = (long)DMODEL * HK;
        wsplit_kernel<<<1024, 256>>>(Wq + l * DK,
            wqkv + (long)l * DMODEL * QKVN, DK / 4, HK / 4, QKVN / 4, 0);
        wsplit_kernel<<<1024, 256>>>(Wk + l * DK,
            wqkv + (long)l * DMODEL * QKVN, DK / 4, HK / 4, QKVN / 4, 1024 / 4);
        wsplit_kernel<<<1024, 256>>>(Wv + l * DK,
            wqkv + (long)l * DMODEL * QKVN, DK / 4, HK / 4, QKVN / 4, 2048 / 4);
        wsplit_kernel<<<1024, 256>>>(Wo + l * DK,
            wo + (long)l * HK * DMODEL, DK / 4, DMODEL / 4, DMODEL / 4, 0);
        long DF = (long)DMODEL * FFDIM;
        wsplit_kernel<<<2048, 256>>>(W1 + l * DF,
            w1 + (long)l * DF, DF / 4, FFDIM / 4, FFDIM / 4, 0);
        wsplit_kernel<<<2048, 256>>>(W2 + l * DF,
            w2 + (long)l * DF, DF / 4, DMODEL / 4, DMODEL / 4, 0);
    }
    wsplit_kernel<<<8192, 256>>>(Wf, wf,
        (long)DMODEL * VOCAB / 4, VOCAB / 4, VOCAB / 4, 0);
    bias_concat_kernel<<<(NLAYER * QKVN + 255) / 256, 256>>>(bq, bk, bv, qkvb);

    // ---- forward ----
    embed_kernel<<<MTOK, 256>>>(tokens, emb, pos, x, xh);

    dim3 gQKV(MTOK / 128, QKVN / 128);
    dim3 gProj(MTOK / 128, DMODEL / 128);
    dim3 gFF1(MTOK / 128, FFDIM / 128);
    dim3 gLogits(MTOK / 128, VOCAB / 128);
    dim3 gAttn(SEQ / 64, BATCH * NHEAD);

    for (int l = 0; l < NLAYER; l++) {
        // qkv = x @ Wqkv + b  (fp32 out)
        hmma_gemm<false, false, true, false><<<gQKV, 256, GEMM_SMEM>>>(
            xh, wqkv + (long)l * DMODEL * QKVN, qkvb + (long)l * QKVN, nullptr,
            qkv, nullptr, QKVN, DMODEL);

        flash_attn_kernel<<<gAttn, 256, FLASH_SMEM>>>(qkv, ah);

        // x = x + a @ Wo + bo  (fp32 + fp16 out)
        hmma_gemm<false, true, true, true><<<gProj, 256, GEMM_SMEM>>>(
            ah, wo + (long)l * HK * DMODEL,
            bo + (long)l * DMODEL, x, x, xh, DMODEL, HK);

        // f = relu(x @ W1 + b1)  (fp16 only)
        hmma_gemm<true, false, false, true><<<gFF1, 256, GEMM_SMEM>>>(
            xh, w1 + (long)l * DMODEL * FFDIM,
            b1 + (long)l * FFDIM, nullptr, nullptr, fh, FFDIM, DMODEL);

        // x = x + f @ W2 + b2
        hmma_gemm<false, true, true, true><<<gProj, 256, GEMM_SMEM>>>(
            fh, w2 + (long)l * FFDIM * DMODEL,
            b2 + (long)l * DMODEL, x, x, xh, DMODEL, FFDIM);
    }

    // logits = x @ Wf + bf
    hmma_gemm<false, false, true, false><<<gLogits, 256, GEMM_SMEM>>>(
        xh, wf, bf, nullptr, out, nullptr, VOCAB, DMODEL);
}

// round 8
// speedup vs baseline: 16.4422x; 1.0583x over previous
#include <cuda_runtime.h>
#include <cuda_fp16.h>
#include <cstdint>

// Problem constants
#define VOCAB 32000
#define DMODEL 1024
#define NHEAD 16
#define HDIM 64
#define FFDIM 4096
#define NLAYER 4
#define SEQ 2048
#define BATCH 2
#define MTOK (BATCH * SEQ)      // 4096 token rows
#define HK (NHEAD * HDIM)       // 1024
#define QKVN 3072               // fused q|k|v output width

// ---------------------------------------------------------------------------
// Scratch (device globals; no allocations allowed)
// ---------------------------------------------------------------------------
__device__ float g_x[MTOK * DMODEL];                 // residual stream fp32
__device__ float g_qkv[MTOK * QKVN];                 // fused qkv fp32
__device__ float g_qkvb[NLAYER * QKVN];              // fused qkv bias
__device__ __half g_xh[MTOK * DMODEL];               // activations fp16
__device__ __half g_ah[MTOK * HK];
__device__ __half g_fh[MTOK * FFDIM];
// fp16 weights, NATURAL [K,N] layout
__device__ __half g_wqkv[NLAYER * DMODEL * QKVN];
__device__ __half g_wo[NLAYER * HK * DMODEL];
__device__ __half g_w1[NLAYER * DMODEL * FFDIM];
__device__ __half g_w2[NLAYER * FFDIM * DMODEL];
__device__ __half g_wf[DMODEL * VOCAB];

// ---------------------------------------------------------------------------
// PTX helpers (all sm_80-era, arch-portable)
// ---------------------------------------------------------------------------
__device__ __forceinline__ uint32_t smem_u32(const void* p) {
    return (uint32_t)__cvta_generic_to_shared(p);
}
__device__ __forceinline__ void cp_async16(uint32_t dst, const void* src) {
    asm volatile("cp.async.cg.shared.global [%0], [%1], 16;\n" :: "r"(dst), "l"(src));
}
__device__ __forceinline__ void cp_commit() { asm volatile("cp.async.commit_group;\n" ::: "memory"); }
template<int N> __device__ __forceinline__ void cp_wait() {
    asm volatile("cp.async.wait_group %0;\n" :: "n"(N) : "memory");
}
__device__ __forceinline__ void ldsm_x4(uint32_t* r, uint32_t addr) {
    asm volatile("ldmatrix.sync.aligned.m8n8.x4.shared.b16 {%0,%1,%2,%3}, [%4];"
                 : "=r"(r[0]), "=r"(r[1]), "=r"(r[2]), "=r"(r[3]) : "r"(addr));
}
__device__ __forceinline__ void ldsm_x4_trans(uint32_t* r, uint32_t addr) {
    asm volatile("ldmatrix.sync.aligned.m8n8.x4.trans.shared.b16 {%0,%1,%2,%3}, [%4];"
                 : "=r"(r[0]), "=r"(r[1]), "=r"(r[2]), "=r"(r[3]) : "r"(addr));
}
__device__ __forceinline__ void mma_f16(float* c, const uint32_t* a, const uint32_t* b) {
    asm volatile(
        "mma.sync.aligned.m16n8k16.row.col.f32.f16.f16.f32 "
        "{%0,%1,%2,%3}, {%4,%5,%6,%7}, {%8,%9}, {%0,%1,%2,%3};"
        : "+f"(c[0]), "+f"(c[1]), "+f"(c[2]), "+f"(c[3])
        : "r"(a[0]), "r"(a[1]), "r"(a[2]), "r"(a[3]), "r"(b[0]), "r"(b[1]));
}

// ---------------------------------------------------------------------------
// Weight convert (NO transpose): W [K,N] fp32 -> fp16 [K,N], optional col pack.
// 2-D grid: blockIdx.x = row, blockIdx.y = column chunk. No int division.
// ---------------------------------------------------------------------------
__global__ void wsplit_kernel(const float* __restrict__ W,
                              __half* __restrict__ Wh,
                              int ncols4, int ostride4, int coff4)
{
    int row = blockIdx.x;
    int c4 = blockIdx.y * blockDim.x + threadIdx.x;
    if (c4 >= ncols4) return;
    float4 v = *(const float4*)(W + ((long)row * ncols4 + c4) * 4);
    __half2 h01, h23;
    h01.x = __float2half_rn(v.x); h01.y = __float2half_rn(v.y);
    h23.x = __float2half_rn(v.z); h23.y = __float2half_rn(v.w);
    __half2* ph = (__half2*)(Wh + ((long)row * ostride4 + coff4 + c4) * 4);
    ph[0] = h01; ph[1] = h23;
}

// ---------------------------------------------------------------------------
// Embedding: x = emb[token] + pos ; also writes fp16
// ---------------------------------------------------------------------------
__global__ void embed_kernel(const int* __restrict__ tokens,
                             const float* __restrict__ emb,
                             const float* __restrict__ pos,
                             float* __restrict__ x,
                             __half* __restrict__ xh)
{
    int row = blockIdx.x;
    int s = row & (SEQ - 1);
    int t = tokens[row];
    const float4* e = (const float4*)(emb + (long)t * DMODEL);
    const float4* p = (const float4*)(pos + (long)s * DMODEL);
    for (int d = threadIdx.x; d < DMODEL / 4; d += blockDim.x) {
        float4 a = e[d], b = p[d];
        a.x += b.x; a.y += b.y; a.z += b.z; a.w += b.w;
        long o = (long)row * DMODEL + d * 4;
        *(float4*)&x[o] = a;
        __half2 h01, h23;
        h01.x = __float2half_rn(a.x); h01.y = __float2half_rn(a.y);
        h23.x = __float2half_rn(a.z); h23.y = __float2half_rn(a.w);
        *(__half2*)&xh[o] = h01; *(__half2*)&xh[o + 2] = h23;
    }
}

// qkv bias concat
__global__ void bias_concat_kernel(const float* __restrict__ bq, const float* __restrict__ bk,
                                   const float* __restrict__ bv, float* __restrict__ out)
{
    int i = blockIdx.x * blockDim.x + threadIdx.x;
    if (i >= NLAYER * QKVN) return;
    int l = i / QKVN, c = i - l * QKVN;
    float v = (c < 1024) ? bq[l * 1024 + c]
            : (c < 2048) ? bk[l * 1024 + c - 1024]
                         : bv[l * 1024 + c - 2048];
    out[i] = v;
}

// ---------------------------------------------------------------------------
// HMMA GEMM: C[M,N] = A[M,K] @ B  (A fp16 [M,K]; B fp16 [K,N] natural)
// Single pass, fp32 accum in registers.
// CTA 128x128, BK=32, 8 warps (2x4), warp tile 64x32, mma.sync m16n8k16.
// B fragments via ldmatrix.x4.trans from [K,N] tiles.
// 4-stage cp.async pipeline; __launch_bounds__(256,2) forces 2 CTAs/SM.
// ---------------------------------------------------------------------------
#define ASTRIDE 80                  // A smem row stride bytes (32 halves + pad)
#define ATILE_B 10240               // [128][40] halves
#define BSTRIDE 272                 // B smem row stride bytes (128 halves + pad)
#define BTILE_B 8704                // [32][136] halves
#define STAGE_B (ATILE_B + BTILE_B)       // 18944
#define GEMM_SMEM (4 * STAGE_B)           // 75776  (x2 CTAs = 151552 < 228KB)

template<bool RELU, bool RESID, bool WF32, bool WH16>
__global__ __launch_bounds__(256, 2)
void hmma_gemm(const __half* __restrict__ A, const __half* __restrict__ B,
               const float* __restrict__ bias, const float* __restrict__ resid,
               float* __restrict__ Cf, __half* __restrict__ Ch,
               int N, int K)
{
    extern __shared__ char smem[];
    uint32_t sbase = smem_u32(smem);

    int tid = threadIdx.x;
    int lane = tid & 31;
    int wid = tid >> 5;
    int wm = wid & 1;          // 2 warps over M (64 rows each)
    int wn = wid >> 1;         // 4 warps over N (32 cols each)
    int row0 = blockIdx.x * 128;
    int ncol0 = blockIdx.y * 128;
    int nk = K >> 5;

    float c[4][4][4];
#pragma unroll
    for (int i = 0; i < 4; i++)
#pragma unroll
        for (int j = 0; j < 4; j++)
#pragma unroll
            for (int k = 0; k < 4; k++) c[i][j][k] = 0.f;

    auto load_stage = [&](int chunk, int buf) {
        uint32_t sb = sbase + buf * STAGE_B;
        int kc = chunk << 5;
        // A: 128 rows x 64B  (512 cp)
#pragma unroll 2
        for (int i = tid; i < 512; i += 256) {
            int r = i >> 2, cc = i & 3;
            cp_async16(sb + (uint32_t)(r * ASTRIDE + cc * 16),
                       A + (long)(row0 + r) * K + kc + cc * 8);
        }
        // B: 32 k-rows x 256B (512 cp)
#pragma unroll 2
        for (int i = tid; i < 512; i += 256) {
            int r = i >> 4, cc = i & 15;
            cp_async16(sb + ATILE_B + (uint32_t)(r * BSTRIDE + cc * 16),
                       B + (long)(kc + r) * N + ncol0 + cc * 8);
        }
        cp_commit();
    };

    load_stage(0, 0);
    load_stage(1, 1);
    load_stage(2, 2);

    // A ldmatrix addressing (row-major, non-trans)
    int arow = (lane & 7) + ((lane >> 3) & 1) * 8;
    int akk = ((lane >> 4) & 1) * 8;
    // B ldmatrix addressing (trans): group t = lane/8
    int bt = lane >> 3, br = lane & 7;
    int brow_off = (bt & 1) * 8 + br;       // k within 16
    int bcol_off = (bt >> 1) * 8;           // n within 16

    for (int ch = 0; ch < nk; ch++) {
        int buf = ch & 3;
        if (ch + 2 < nk)      cp_wait<2>();
        else if (ch + 1 < nk) cp_wait<1>();
        else                  cp_wait<0>();
        __syncthreads();
        if (ch + 3 < nk) load_stage(ch + 3, (ch + 3) & 3);

        uint32_t sb = sbase + buf * STAGE_B;
#pragma unroll
        for (int ks = 0; ks < 2; ks++) {
            int k0 = ks * 16;
            uint32_t a_r[4][4], b_r[4][2];
#pragma unroll
            for (int mi = 0; mi < 4; mi++) {
                uint32_t ad = sb + (uint32_t)((wm * 64 + mi * 16 + arow) * ASTRIDE
                                              + (k0 + akk) * 2);
                ldsm_x4(a_r[mi], ad);
            }
#pragma unroll
            for (int p = 0; p < 2; p++) {
                uint32_t bd = sb + ATILE_B
                            + (uint32_t)((k0 + brow_off) * BSTRIDE
                                         + (wn * 32 + p * 16 + bcol_off) * 2);
                uint32_t r[4];
                ldsm_x4_trans(r, bd);
                b_r[2 * p][0] = r[0]; b_r[2 * p][1] = r[1];
                b_r[2 * p + 1][0] = r[2]; b_r[2 * p + 1][1] = r[3];
            }
#pragma unroll
            for (int mi = 0; mi < 4; mi++)
#pragma unroll
                for (int ni = 0; ni < 4; ni++)
                    mma_f16(c[mi][ni], a_r[mi], b_r[ni]);
        }
    }

    // Epilogue
    int rbase = row0 + wm * 64 + (lane >> 2);
    int cbase = ncol0 + wn * 32 + (lane & 3) * 2;
#pragma unroll
    for (int mi = 0; mi < 4; mi++) {
#pragma unroll
        for (int ni = 0; ni < 4; ni++) {
            int gc = cbase + ni * 8;
            float b0 = __ldg(&bias[gc]), b1 = __ldg(&bias[gc + 1]);
#pragma unroll
            for (int half_ = 0; half_ < 2; half_++) {
                long gr = rbase + mi * 16 + half_ * 8;
                float v0 = c[mi][ni][half_ * 2 + 0] + b0;
                float v1 = c[mi][ni][half_ * 2 + 1] + b1;
                if (RELU) { v0 = fmaxf(v0, 0.f); v1 = fmaxf(v1, 0.f); }
                if (RESID) {
                    float2 rr = *(const float2*)&resid[gr * N + gc];
                    v0 += rr.x; v1 += rr.y;
                }
                if (WF32) {
                    float2 o; o.x = v0; o.y = v1;
                    *(float2*)&Cf[gr * N + gc] = o;
                }
                if (WH16) {
                    __half2 hh;
                    hh.x = __float2half_rn(v0); hh.y = __float2half_rn(v1);
                    *(__half2*)&Ch[gr * N + gc] = hh;
                }
            }
        }
    }
}

// ---------------------------------------------------------------------------
// Flash attention (fp32), reads fused qkv [M,3072], writes fp16 attn out
// ---------------------------------------------------------------------------
#define FPAD 68

__global__ __launch_bounds__(256)
void flash_attn_kernel(const float* __restrict__ QKV,
                       __half* __restrict__ Ao)
{
    extern __shared__ float sm[];
    float* Qs = sm;
    float* Ks = sm + 64 * FPAD;
    float* Vs = sm + 2 * 64 * FPAD;
    float* Ps = sm + 3 * 64 * FPAD;

    int qt = gridDim.x - 1 - blockIdx.x;
    int bh = blockIdx.y;
    int b = bh >> 4;
    int h = bh & 15;
    int tid = threadIdx.x;
    int tx = tid & 15;
    int ty = tid >> 4;

    long baseq = (long)b * SEQ * QKVN + h * HDIM;
    long basek = baseq + 1024;
    long basev = baseq + 2048;

    for (int i = tid; i < 64 * 16; i += 256) {
        int r = i >> 4, c4 = (i & 15) * 4;
        *(float4*)&Qs[r * FPAD + c4] =
            *(const float4*)&QKV[baseq + (long)(qt * 64 + r) * QKVN + c4];
    }

    float m[4], l[4], o[4][4];
#pragma unroll
    for (int i = 0; i < 4; i++) {
        m[i] = -1e30f; l[i] = 0.f;
#pragma unroll
        for (int j = 0; j < 4; j++) o[i][j] = 0.f;
    }

    for (int jt = 0; jt <= qt; jt++) {
        for (int i = tid; i < 64 * 16; i += 256) {
            int r = i >> 4, c4 = (i & 15) * 4;
            long off = (long)(jt * 64 + r) * QKVN + c4;
            *(float4*)&Ks[r * FPAD + c4] = *(const float4*)&QKV[basek + off];
            *(float4*)&Vs[r * FPAD + c4] = *(const float4*)&QKV[basev + off];
        }
        __syncthreads();

        float s[4][4];
#pragma unroll
        for (int i = 0; i < 4; i++)
#pragma unroll
            for (int j = 0; j < 4; j++) s[i][j] = 0.f;

#pragma unroll 4
        for (int k4 = 0; k4 < HDIM; k4 += 4) {
            float4 qv[4], kv[4];
#pragma unroll
            for (int i = 0; i < 4; i++)
                qv[i] = *(const float4*)&Qs[(ty * 4 + i) * FPAD + k4];
#pragma unroll
            for (int j = 0; j < 4; j++)
                kv[j] = *(const float4*)&Ks[(tx + 16 * j) * FPAD + k4];
#pragma unroll
            for (int i = 0; i < 4; i++)
#pragma unroll
                for (int j = 0; j < 4; j++) {
                    s[i][j] = fmaf(qv[i].x, kv[j].x, s[i][j]);
                    s[i][j] = fmaf(qv[i].y, kv[j].y, s[i][j]);
                    s[i][j] = fmaf(qv[i].z, kv[j].z, s[i][j]);
                    s[i][j] = fmaf(qv[i].w, kv[j].w, s[i][j]);
                }
        }

        if (jt == qt) {
#pragma unroll
            for (int i = 0; i < 4; i++) {
                int qloc = ty * 4 + i;
#pragma unroll
                for (int j = 0; j < 4; j++) {
                    int kloc = tx + 16 * j;
                    s[i][j] = (kloc > qloc) ? -1e30f : s[i][j] * 0.125f;
                }
            }
        } else {
#pragma unroll
            for (int i = 0; i < 4; i++)
#pragma unroll
                for (int j = 0; j < 4; j++) s[i][j] *= 0.125f;
        }

#pragma unroll
        for (int i = 0; i < 4; i++) {
            float rmax = fmaxf(fmaxf(s[i][0], s[i][1]), fmaxf(s[i][2], s[i][3]));
#pragma unroll
            for (int w = 1; w < 16; w <<= 1)
                rmax = fmaxf(rmax, __shfl_xor_sync(0xffffffffu, rmax, w));
            float mn = fmaxf(m[i], rmax);
            float corr = __expf(m[i] - mn);
            float rsum = 0.f;
#pragma unroll
            for (int j = 0; j < 4; j++) {
                float p = __expf(s[i][j] - mn);
                s[i][j] = p;
                rsum += p;
            }
#pragma unroll
            for (int w = 1; w < 16; w <<= 1)
                rsum += __shfl_xor_sync(0xffffffffu, rsum, w);
            l[i] = l[i] * corr + rsum;
            m[i] = mn;
#pragma unroll
            for (int j = 0; j < 4; j++) o[i][j] *= corr;
        }

#pragma unroll
        for (int i = 0; i < 4; i++)
#pragma unroll
            for (int j = 0; j < 4; j++)
                Ps[(ty * 4 + i) * FPAD + tx + 16 * j] = s[i][j];
        __syncthreads();

#pragma unroll 4
        for (int k4 = 0; k4 < 64; k4 += 4) {
            float4 pv[4];
#pragma unroll
            for (int i = 0; i < 4; i++)
                pv[i] = *(const float4*)&Ps[(ty * 4 + i) * FPAD + k4];
#pragma unroll
            for (int cc = 0; cc < 4; cc++) {
                float4 vv = *(const float4*)&Vs[(k4 + cc) * FPAD + tx * 4];
#pragma unroll
                for (int i = 0; i < 4; i++) {
                    float p = (cc == 0) ? pv[i].x : (cc == 1) ? pv[i].y
                              : (cc == 2) ? pv[i].z : pv[i].w;
                    o[i][0] = fmaf(p, vv.x, o[i][0]);
                    o[i][1] = fmaf(p, vv.y, o[i][1]);
                    o[i][2] = fmaf(p, vv.z, o[i][2]);
                    o[i][3] = fmaf(p, vv.w, o[i][3]);
                }
            }
        }
        __syncthreads();
    }

#pragma unroll
    for (int i = 0; i < 4; i++) {
        float inv = 1.0f / l[i];
        int qg = qt * 64 + ty * 4 + i;
        __half2 h01, h23;
        h01.x = __float2half_rn(o[i][0] * inv);
        h01.y = __float2half_rn(o[i][1] * inv);
        h23.x = __float2half_rn(o[i][2] * inv);
        h23.y = __float2half_rn(o[i][3] * inv);
        long oaddr = (long)(b * SEQ + qg) * HK + h * HDIM + tx * 4;
        *(__half2*)&Ao[oaddr] = h01; *(__half2*)&Ao[oaddr + 2] = h23;
    }
}

#define FLASH_SMEM (4 * 64 * FPAD * 4)

// ---------------------------------------------------------------------------
// Launch
// ---------------------------------------------------------------------------
extern "C" void kernel_launch(void* const* d_in, const int* in_sizes, int n_in,
                              void* d_out, int out_size)
{
    const int*   tokens = (const int*)  d_in[0];
    const float* emb    = (const float*)d_in[1];
    const float* pos    = (const float*)d_in[2];
    const float* Wq     = (const float*)d_in[3];
    const float* bq     = (const float*)d_in[4];
    const float* Wk     = (const float*)d_in[5];
    const float* bk     = (const float*)d_in[6];
    const float* Wv     = (const float*)d_in[7];
    const float* bv     = (const float*)d_in[8];
    const float* Wo     = (const float*)d_in[9];
    const float* bo     = (const float*)d_in[10];
    const float* W1     = (const float*)d_in[11];
    const float* b1     = (const float*)d_in[12];
    const float* W2     = (const float*)d_in[13];
    const float* b2     = (const float*)d_in[14];
    const float* Wf     = (const float*)d_in[15];
    const float* bf     = (const float*)d_in[16];
    float* out = (float*)d_out;

    float *x, *qkv, *qkvb;
    __half *xh, *ah, *fh;
    __half *wqkv, *wo, *w1, *w2, *wf;
    cudaGetSymbolAddress((void**)&x, g_x);
    cudaGetSymbolAddress((void**)&qkv, g_qkv);
    cudaGetSymbolAddress((void**)&qkvb, g_qkvb);
    cudaGetSymbolAddress((void**)&xh, g_xh);
    cudaGetSymbolAddress((void**)&ah, g_ah);
    cudaGetSymbolAddress((void**)&fh, g_fh);
    cudaGetSymbolAddress((void**)&wqkv, g_wqkv);
    cudaGetSymbolAddress((void**)&wo, g_wo);
    cudaGetSymbolAddress((void**)&w1, g_w1);
    cudaGetSymbolAddress((void**)&w2, g_w2);
    cudaGetSymbolAddress((void**)&wf, g_wf);

    static bool attr_set = false;
    if (!attr_set) {
        cudaFuncSetAttribute(flash_attn_kernel,
                             cudaFuncAttributeMaxDynamicSharedMemorySize, FLASH_SMEM);
        cudaFuncSetAttribute(hmma_gemm<false, false, true, false>,
                             cudaFuncAttributeMaxDynamicSharedMemorySize, GEMM_SMEM);
        cudaFuncSetAttribute(hmma_gemm<false, true, true, true>,
                             cudaFuncAttributeMaxDynamicSharedMemorySize, GEMM_SMEM);
        cudaFuncSetAttribute(hmma_gemm<true, false, false, true>,
                             cudaFuncAttributeMaxDynamicSharedMemorySize, GEMM_SMEM);
        attr_set = true;
    }

    // ---- weight convert (no transpose; [K,N] natural layout) ----
    for (int l = 0; l < NLAYER; l++) {
        wsplit_kernel<<<dim3(DMODEL, 1), 256>>>(Wq + (long)l * DMODEL * HK,
            wqkv + (long)l * DMODEL * QKVN, HK / 4, QKVN / 4, 0);
        wsplit_kernel<<<dim3(DMODEL, 1), 256>>>(Wk + (long)l * DMODEL * HK,
            wqkv + (long)l * DMODEL * QKVN, HK / 4, QKVN / 4, 1024 / 4);
        wsplit_kernel<<<dim3(DMODEL, 1), 256>>>(Wv + (long)l * DMODEL * HK,
            wqkv + (long)l * DMODEL * QKVN, HK / 4, QKVN / 4, 2048 / 4);
        wsplit_kernel<<<dim3(HK, 1), 256>>>(Wo + (long)l * HK * DMODEL,
            wo + (long)l * HK * DMODEL, DMODEL / 4, DMODEL / 4, 0);
        wsplit_kernel<<<dim3(DMODEL, 4), 256>>>(W1 + (long)l * DMODEL * FFDIM,
            w1 + (long)l * DMODEL * FFDIM, FFDIM / 4, FFDIM / 4, 0);
        wsplit_kernel<<<dim3(FFDIM, 1), 256>>>(W2 + (long)l * FFDIM * DMODEL,
            w2 + (long)l * FFDIM * DMODEL, DMODEL / 4, DMODEL / 4, 0);
    }
    wsplit_kernel<<<dim3(DMODEL, 32), 256>>>(Wf, wf, VOCAB / 4, VOCAB / 4, 0);
    bias_concat_kernel<<<(NLAYER * QKVN + 255) / 256, 256>>>(bq, bk, bv, qkvb);

    // ---- forward ----
    embed_kernel<<<MTOK, 256>>>(tokens, emb, pos, x, xh);

    dim3 gQKV(MTOK / 128, QKVN / 128);
    dim3 gProj(MTOK / 128, DMODEL / 128);
    dim3 gFF1(MTOK / 128, FFDIM / 128);
    dim3 gLogits(MTOK / 128, VOCAB / 128);
    dim3 gAttn(SEQ / 64, BATCH * NHEAD);

    for (int l = 0; l < NLAYER; l++) {
        // qkv = x @ Wqkv + b  (fp32 out)
        hmma_gemm<false, false, true, false><<<gQKV, 256, GEMM_SMEM>>>(
            xh, wqkv + (long)l * DMODEL * QKVN, qkvb + (long)l * QKVN, nullptr,
            qkv, nullptr, QKVN, DMODEL);

        flash_attn_kernel<<<gAttn, 256, FLASH_SMEM>>>(qkv, ah);

        // x = x + a @ Wo + bo  (fp32 + fp16 out)
        hmma_gemm<false, true, true, true><<<gProj, 256, GEMM_SMEM>>>(
            ah, wo + (long)l * HK * DMODEL,
            bo + (long)l * DMODEL, x, x, xh, DMODEL, HK);

        // f = relu(x @ W1 + b1)  (fp16 only)
        hmma_gemm<true, false, false, true><<<gFF1, 256, GEMM_SMEM>>>(
            xh, w1 + (long)l * DMODEL * FFDIM,
            b1 + (long)l * FFDIM, nullptr, nullptr, fh, FFDIM, DMODEL);

        // x = x + f @ W2 + b2
        hmma_gemm<false, true, true, true><<<gProj, 256, GEMM_SMEM>>>(
            fh, w2 + (long)l * FFDIM * DMODEL,
            b2 + (long)l * DMODEL, x, x, xh, DMODEL, FFDIM);
    }

    // logits = x @ Wf + bf
    hmma_gemm<false, false, true, false><<<gLogits, 256, GEMM_SMEM>>>(
        xh, wf, bf, nullptr, out, nullptr, VOCAB, DMODEL);
}